// round 12
// baseline (speedup 1.0000x reference)
#include <cuda_runtime.h>
#include <cuda_bf16.h>
#include <cstdint>

#define TV 8192
#define BHV 32
#define LN_EPS 1e-5f
#define DEN_EPS 1e-6f
#define RSB 144     // plane row stride bytes (72 bf16)
#define PL  9216    // hi->lo plane delta, bytes
#define TPC 8       // 64-token tiles per CTA

// Scratch (allocation-free)
__device__ uint32_t g_kp[(size_t)BHV * TV * 32];            // 32 MB kp 2xbf16 [bh][t][m/2]
__device__ float    g_part[(size_t)BHV * 16 * 4096];        // 8 MB partial kv
__device__ __align__(16) uint32_t g_pjh[2304];              // packed proj plane [m][n]
__device__ __align__(16) uint32_t g_kvh[(size_t)BHV * 2304];
__device__ __align__(16) uint32_t g_kvl[(size_t)BHV * 2304];

// ---------------- helpers ----------------
__device__ __forceinline__ uint32_t smem_u32(const void* p) {
    uint32_t a;
    asm("{ .reg .u64 t; cvta.to.shared.u64 t, %1; cvt.u32.u64 %0, t; }" : "=r"(a) : "l"(p));
    return a;
}
__device__ __forceinline__ float featexp(float x) {
    return __expf(fminf(fmaxf(x, -15.f), 15.f)) * 0.1f;
}
__device__ __forceinline__ float qred(float v) {
    v += __shfl_xor_sync(0xffffffffu, v, 1);
    v += __shfl_xor_sync(0xffffffffu, v, 2);
    return v;
}
__device__ __forceinline__ uint32_t pack2(float x, float y) {
    __nv_bfloat162 b = __floats2bfloat162_rn(x, y);
    return *(uint32_t*)&b;
}
__device__ __forceinline__ float2 unpk2(uint32_t p) {
    __nv_bfloat162 b = *(__nv_bfloat162*)&p;
    return make_float2(__bfloat162float(b.x), __bfloat162float(b.y));
}
__device__ __forceinline__ void packhl2(float a, float b, uint32_t& hi, uint32_t& lo) {
    __nv_bfloat16 ha = __float2bfloat16_rn(a), hb = __float2bfloat16_rn(b);
    __nv_bfloat16 la = __float2bfloat16_rn(a - __bfloat162float(ha));
    __nv_bfloat16 lb = __float2bfloat16_rn(b - __bfloat162float(hb));
    hi = (uint32_t)__bfloat16_as_ushort(ha) | ((uint32_t)__bfloat16_as_ushort(hb) << 16);
    lo = (uint32_t)__bfloat16_as_ushort(la) | ((uint32_t)__bfloat16_as_ushort(lb) << 16);
}
__device__ __forceinline__ void ldsm4(uint32_t* r, uint32_t a) {
    asm volatile("ldmatrix.sync.aligned.m8n8.x4.shared.b16 {%0,%1,%2,%3}, [%4];"
        : "=r"(r[0]), "=r"(r[1]), "=r"(r[2]), "=r"(r[3]) : "r"(a));
}
__device__ __forceinline__ void ldsm4t(uint32_t* r, uint32_t a) {
    asm volatile("ldmatrix.sync.aligned.m8n8.x4.trans.shared.b16 {%0,%1,%2,%3}, [%4];"
        : "=r"(r[0]), "=r"(r[1]), "=r"(r[2]), "=r"(r[3]) : "r"(a));
}
__device__ __forceinline__ void mma_bf16(float* c, const uint32_t* a, uint32_t b0, uint32_t b1) {
    asm("mma.sync.aligned.m16n8k16.row.col.f32.bf16.bf16.f32 "
        "{%0,%1,%2,%3},{%4,%5,%6,%7},{%8,%9},{%0,%1,%2,%3};"
        : "+f"(c[0]), "+f"(c[1]), "+f"(c[2]), "+f"(c[3])
        : "r"(a[0]), "r"(a[1]), "r"(a[2]), "r"(a[3]), "r"(b0), "r"(b1));
}
__device__ __forceinline__ void mma3(float* c, const uint32_t* Ah, const uint32_t* Al,
                                     uint32_t bh0, uint32_t bh1, uint32_t bl0, uint32_t bl1) {
    mma_bf16(c, Ah, bh0, bh1);
    mma_bf16(c, Ah, bl0, bl1);
    mma_bf16(c, Al, bh0, bh1);
}
__device__ __forceinline__ void ln16(float* x, const float* GB, int c0) {
    float s = 0.f, ss = 0.f;
#pragma unroll
    for (int j = 0; j < 16; j++) { s += x[j]; ss += x[j] * x[j]; }
    s = qred(s); ss = qred(ss);
    float mu = s * (1.f / 64.f);
    float rstd = rsqrtf(ss * (1.f / 64.f) - mu * mu + LN_EPS);
#pragma unroll
    for (int j = 0; j < 16; j++)
        x[j] = (x[j] - mu) * rstd * GB[c0 + j] + GB[64 + c0 + j];
}

// pass1 byte offsets (EXACT R10/R11)
#define P1_KN  0
#define P1_KPH 9216
#define P1_KPL 18432
#define P1_PJ  27648
#define P1_VTH 36864
#define P1_VTL 46080
#define P1_GB  55296
#define P1_BYTES 55808
// pass2 byte offsets (EXACT R9/R10/R11)
#define P2_QNH 0       // QN single plane, overlaid by qp-hi
#define P2_QPL 9216    // qp-lo
#define P2_PJ  18432
#define P2_KVH 27648
#define P2_KVL 36864
#define P2_DEN 46080
#define P2_PD  46592   // 256 x float2
#define P2_GB  48640
#define P2_BYTES 49152

// ---------------------------------------------------------------------------
extern "C" __global__ void fa_setup(const float* __restrict__ proj)
{
    const int tid = threadIdx.x;
    for (int i = tid; i < 2048; i += 256) {
        int m = i & 63, nw = i >> 6;
        g_pjh[m * 36 + nw] = pack2(proj[(2 * nw) * 64 + m], proj[(2 * nw + 1) * 64 + m]);
    }
}

// ---------------------------------------------------------------------------
// Pass 1: R10/R11 structure (2 syncs/tile) + next-tile k L2-prefetch.
// ---------------------------------------------------------------------------
extern "C" __global__ void __launch_bounds__(256, 4) fa_pass1(
    const float* __restrict__ k, const float* __restrict__ v,
    const float* __restrict__ gamma, const float* __restrict__ beta)
{
    extern __shared__ char sm[];
    const uint32_t sb = smem_u32(sm);
    float* GB = (float*)(sm + P1_GB);

    const int tid = threadIdx.x, lane = tid & 31, wid = tid >> 5;
    const int bh = blockIdx.y, bx = blockIdx.x;
    const int t = tid >> 2, c0 = (tid & 3) * 16;

    if (tid < 64) GB[tid] = gamma[tid];
    else if (tid < 128) GB[tid] = beta[tid - 64];
    {
        const uint4* src = (const uint4*)g_pjh;
        uint4* dst = (uint4*)(sm + P1_PJ);
        for (int i = tid; i < 576; i += 256) dst[i] = src[i];
    }
    __syncthreads();

    const int r = lane >> 2, qk = (lane & 3) * 2;
    const int mb = wid & 3, nh = wid >> 2;
    const int tr = mb * 16 + r;
    const int l7 = lane & 7, l8 = (lane >> 3) & 1, l16 = (lane >> 4) & 1;

    const uint32_t aG1 = sb + P1_KN + (mb * 16 + l7 + l8 * 8) * RSB + l16 * 16;
    const uint32_t bG1 = sb + P1_PJ + (nh * 32 + l7 + l16 * 8) * RSB + l8 * 16;
    const uint32_t aG2 = sb + P1_KPH + (l7 + l16 * 8) * RSB + (mb * 16 + l8 * 8) * 2;
    const uint32_t bG2 = sb + P1_VTH + (l7 + l8 * 8) * RSB + (nh * 32 + l16 * 8) * 2;

    float acc2[4][4];
#pragma unroll
    for (int f = 0; f < 4; f++)
#pragma unroll
        for (int j = 0; j < 4; j++) acc2[f][j] = 0.f;

    for (int it = 0; it < TPC; ++it) {
        const int t0 = (bx * TPC + it) * 64;
        const float* kr = k + ((size_t)(bh * TV + t0 + t)) * 64 + c0;
        const float* vr = v + ((size_t)(bh * TV + t0 + t)) * 64 + c0;

        // ---- Phase 1: LN(k)+L2 -> KN; L2-prefetch v + next k ----
        {
            asm volatile("prefetch.global.L2 [%0];" :: "l"(vr));
            if (it + 1 < TPC)
                asm volatile("prefetch.global.L2 [%0];" :: "l"(kr + 4096));
            float xk[16];
#pragma unroll
            for (int i = 0; i < 4; i++) *(float4*)(xk + 4 * i) = *(const float4*)(kr + 4 * i);
            ln16(xk, GB, c0);
            float n2 = 0.f;
#pragma unroll
            for (int j = 0; j < 16; j++) n2 += xk[j] * xk[j];
            n2 = qred(n2);
            float inv = 1.f / fmaxf(sqrtf(n2), 1e-12f);
#pragma unroll
            for (int jj = 0; jj < 8; jj++)
                *(uint32_t*)(sm + P1_KN + t * RSB + (c0 + 2 * jj) * 2) =
                    pack2(xk[2 * jj] * inv, xk[2 * jj + 1] * inv);
        }
        __syncthreads();   // S1

        // ---- Phase 2: GEMM1 single-bf16 ----
        float acc[4][4];
#pragma unroll
        for (int f = 0; f < 4; f++)
#pragma unroll
            for (int j = 0; j < 4; j++) acc[f][j] = 0.f;
#pragma unroll
        for (int ks = 0; ks < 4; ks++) {
            uint32_t Ah[4];
            ldsm4(Ah, aG1 + ks * 32);
#pragma unroll
            for (int f2 = 0; f2 < 2; f2++) {
                uint32_t Bh[4];
                ldsm4(Bh, bG1 + f2 * 16 * RSB + ks * 32);
                mma_bf16(acc[f2 * 2],     Ah, Bh[0], Bh[1]);
                mma_bf16(acc[f2 * 2 + 1], Ah, Bh[2], Bh[3]);
            }
        }

        // ---- Phase 3: kp = featexp(D1) -> g_kp + KP hi/lo planes ----
        {
            uint32_t* gkp = g_kp + ((size_t)bh * TV + t0) * 32;
#pragma unroll
            for (int f = 0; f < 4; f++) {
                float x0 = featexp(acc[f][0]), x1 = featexp(acc[f][1]);
                float x2 = featexp(acc[f][2]), x3 = featexp(acc[f][3]);
                int c = nh * 32 + f * 8 + qk;
                gkp[tr * 32 + (c >> 1)] = pack2(x0, x1);
                gkp[(tr + 8) * 32 + (c >> 1)] = pack2(x2, x3);
                uint32_t hi, lo;
                packhl2(x0, x1, hi, lo);
                *(uint32_t*)(sm + P1_KPH + tr * RSB + c * 2) = hi;
                *(uint32_t*)(sm + P1_KPL + tr * RSB + c * 2) = lo;
                packhl2(x2, x3, hi, lo);
                *(uint32_t*)(sm + P1_KPH + (tr + 8) * RSB + c * 2) = hi;
                *(uint32_t*)(sm + P1_KPL + (tr + 8) * RSB + c * 2) = lo;
            }
        }

        // ---- Phase 4: LN(v) -> VT hi/lo ----
        {
            float xv[16];
#pragma unroll
            for (int i = 0; i < 4; i++) *(float4*)(xv + 4 * i) = *(const float4*)(vr + 4 * i);
            ln16(xv, GB, c0);
#pragma unroll
            for (int jj = 0; jj < 8; jj++) {
                uint32_t hi, lo;
                packhl2(xv[2 * jj], xv[2 * jj + 1], hi, lo);
                *(uint32_t*)(sm + P1_VTH + t * RSB + (c0 + 2 * jj) * 2) = hi;
                *(uint32_t*)(sm + P1_VTL + t * RSB + (c0 + 2 * jj) * 2) = lo;
            }
        }
        __syncthreads();   // S2

        // ---- Phase 5: GEMM2 3-term ----
#pragma unroll
        for (int ks = 0; ks < 4; ks++) {
            uint32_t Ah[4], Al[4];
            ldsm4t(Ah, aG2 + ks * 16 * RSB);
            ldsm4t(Al, aG2 + PL + ks * 16 * RSB);
#pragma unroll
            for (int f2 = 0; f2 < 2; f2++) {
                uint32_t Bh[4], Bl[4];
                ldsm4t(Bh, bG2 + f2 * 32 + ks * 16 * RSB);
                ldsm4t(Bl, bG2 + PL + f2 * 32 + ks * 16 * RSB);
                mma3(acc2[f2 * 2],     Ah, Al, Bh[0], Bh[1], Bl[0], Bl[1]);
                mma3(acc2[f2 * 2 + 1], Ah, Al, Bh[2], Bh[3], Bl[2], Bl[3]);
            }
        }
    }

    float* gp = g_part + (size_t)(bh * 16 + bx) * 4096;
#pragma unroll
    for (int f = 0; f < 4; f++) {
        int n = nh * 32 + f * 8 + qk;
        *(float2*)(gp + tr * 64 + n) = make_float2(acc2[f][0], acc2[f][1]);
        *(float2*)(gp + (tr + 8) * 64 + n) = make_float2(acc2[f][2], acc2[f][3]);
    }
}

// ---------------------------------------------------------------------------
extern "C" __global__ void __launch_bounds__(256) fa_reduce()
{
    const int tid = blockIdx.x * 256 + threadIdx.x;
    const int bh = tid >> 10, e4 = tid & 1023;
    const float4* p = (const float4*)(g_part + (size_t)bh * 16 * 4096) + e4;
    float4 s = make_float4(0.f, 0.f, 0.f, 0.f);
#pragma unroll
    for (int c = 0; c < 16; ++c) {
        float4 a = p[(size_t)c * 1024];
        s.x += a.x; s.y += a.y; s.z += a.z; s.w += a.w;
    }
    s.x *= 0.1f; s.y *= 0.1f; s.z *= 0.1f; s.w *= 0.1f;
    const int m = e4 >> 4, n0 = (e4 & 15) * 4;
    const int base = bh * 2304 + m * 36 + (n0 >> 1);
    uint32_t hi, lo;
    packhl2(s.x, s.y, hi, lo);
    g_kvh[base] = hi; g_kvl[base] = lo;
    packhl2(s.z, s.w, hi, lo);
    g_kvh[base + 1] = hi; g_kvl[base + 1] = lo;
}

// ---------------------------------------------------------------------------
// Pass 2: R11 pairwise-decoupled structure + hoisted g_kp loads + q prefetch.
// ---------------------------------------------------------------------------
extern "C" __global__ void __launch_bounds__(256, 4) fa_pass2(
    const float* __restrict__ q, const float* __restrict__ gamma,
    const float* __restrict__ beta, float* __restrict__ out)
{
    extern __shared__ char sm[];
    const uint32_t sb = smem_u32(sm);
    float*  DEN = (float*)(sm + P2_DEN);
    float2* PD  = (float2*)(sm + P2_PD);
    float*  GB  = (float*)(sm + P2_GB);

    const int tid = threadIdx.x, lane = tid & 31, wid = tid >> 5;
    const int bh = blockIdx.y, bx = blockIdx.x;
    const int mb = wid & 3, nh = wid >> 2;
    const int t = mb * 16 + nh * 8 + (lane >> 2);
    const int c0 = (lane & 3) * 16;

    if (tid < 64) GB[tid] = gamma[tid];
    else if (tid < 128) GB[tid] = beta[tid - 64];
    {
        const uint4* src = (const uint4*)g_pjh;
        uint4* dst = (uint4*)(sm + P2_PJ);
        for (int i = tid; i < 576; i += 256) dst[i] = src[i];
        const uint4* kh = (const uint4*)(g_kvh + bh * 2304);
        const uint4* kl = (const uint4*)(g_kvl + bh * 2304);
        uint4* dh = (uint4*)(sm + P2_KVH);
        uint4* dl = (uint4*)(sm + P2_KVL);
        for (int i = tid; i < 576; i += 256) { dh[i] = kh[i]; dl[i] = kl[i]; }
    }
    __syncthreads();

    const int r = lane >> 2, qk = (lane & 3) * 2;
    const int tr = mb * 16 + r;
    const int l7 = lane & 7, l8 = (lane >> 3) & 1, l16 = (lane >> 4) & 1;

    const uint32_t aG3 = sb + P2_QNH + (mb * 16 + l7 + l8 * 8) * RSB + l16 * 16;
    const uint32_t bG3 = sb + P2_PJ + (nh * 32 + l7 + l16 * 8) * RSB + l8 * 16;
    const uint32_t bG4 = sb + P2_KVH + (l7 + l8 * 8) * RSB + (nh * 32 + l16 * 8) * 2;

#define PAIRBAR() asm volatile("bar.sync %0, 64;" :: "r"(mb + 1) : "memory")

    for (int it = 0; it < TPC; ++it) {
        const int t0 = (bx * TPC + it) * 64;
        float x[16];

        // ---- hoisted g_kp loads for this tile (consumed in epi3) ----
        uint32_t kpr[16];
        {
            const uint32_t* gkp = g_kp + ((size_t)bh * TV + t0) * 32;
#pragma unroll
            for (int f = 0; f < 8; f++) {
                int cw = f * 4 + (qk >> 1);
                kpr[f * 2]     = gkp[tr * 32 + cw];
                kpr[f * 2 + 1] = gkp[(tr + 8) * 32 + cw];
            }
        }

        // ---- LN + L2 of q -> QN rows of this pair; prefetch next q ----
        {
            const float* qr = q + ((size_t)(bh * TV + t0 + t)) * 64 + c0;
            if (it + 1 < TPC)
                asm volatile("prefetch.global.L2 [%0];" :: "l"(qr + 4096));
#pragma unroll
            for (int i = 0; i < 4; i++) *(float4*)(x + 4 * i) = *(const float4*)(qr + 4 * i);
            ln16(x, GB, c0);
            float n2 = 0.f;
#pragma unroll
            for (int j = 0; j < 16; j++) n2 += x[j] * x[j];
            n2 = qred(n2);
            float inv = 1.f / fmaxf(sqrtf(n2), 1e-12f);
#pragma unroll
            for (int jj = 0; jj < 8; jj++)
                *(uint32_t*)(sm + P2_QNH + t * RSB + (c0 + 2 * jj) * 2) =
                    pack2(x[2 * jj] * inv, x[2 * jj + 1] * inv);
        }
        PAIRBAR();   // B1

        // ---- GEMM3 single-bf16: D3[t][m] = QN @ PJ^T ----
        float acc[4][4];
#pragma unroll
        for (int f = 0; f < 4; f++)
#pragma unroll
            for (int j = 0; j < 4; j++) acc[f][j] = 0.f;
#pragma unroll
        for (int ks = 0; ks < 4; ks++) {
            uint32_t Ah[4];
            ldsm4(Ah, aG3 + ks * 32);
#pragma unroll
            for (int f2 = 0; f2 < 2; f2++) {
                uint32_t Bh[4];
                ldsm4(Bh, bG3 + f2 * 16 * RSB + ks * 32);
                mma_bf16(acc[f2 * 2],     Ah, Bh[0], Bh[1]);
                mma_bf16(acc[f2 * 2 + 1], Ah, Bh[2], Bh[3]);
            }
        }
        PAIRBAR();   // B2

        // ---- qp = featexp(D3) -> planes; denom partials vs hoisted kp ----
        {
            float den0 = 0.f, den1 = 0.f;
#pragma unroll
            for (int f = 0; f < 4; f++) {
                float x0 = featexp(acc[f][0]), x1 = featexp(acc[f][1]);
                float x2 = featexp(acc[f][2]), x3 = featexp(acc[f][3]);
                int c = nh * 32 + f * 8 + qk;
                uint32_t hi, lo;
                packhl2(x0, x1, hi, lo);
                *(uint32_t*)(sm + P2_QNH + tr * RSB + c * 2) = hi;
                *(uint32_t*)(sm + P2_QPL + tr * RSB + c * 2) = lo;
                packhl2(x2, x3, hi, lo);
                *(uint32_t*)(sm + P2_QNH + (tr + 8) * RSB + c * 2) = hi;
                *(uint32_t*)(sm + P2_QPL + (tr + 8) * RSB + c * 2) = lo;
                // kp fragment index: epi3's f here maps to kpr slots 2f (row tr)
                // and 2f+1 (row tr+8), loaded with cw = (nh*32+f*8+qk)>>1?  No:
                // hoist loop used cw = f*4 + (qk>>1) over f<8; epi3 f<4 maps to
                // hoist f' = nh*4 + f  ->  cw = (nh*32+f*8+qk)>>1 exactly.
                float2 k0 = unpk2(kpr[(nh * 4 + f) * 2]);
                float2 k1 = unpk2(kpr[(nh * 4 + f) * 2 + 1]);
                den0 += x0 * k0.x + x1 * k0.y;
                den1 += x2 * k1.x + x3 * k1.y;
            }
            den0 = qred(den0);
            den1 = qred(den1);
            if ((lane & 3) == 0) { DEN[nh * 64 + tr] = den0; DEN[nh * 64 + tr + 8] = den1; }
        }
        PAIRBAR();   // B3

        // ---- GEMM4 3-term: D4[t][n] = qp @ kv ----
        float acc2[4][4];
#pragma unroll
        for (int f = 0; f < 4; f++)
#pragma unroll
            for (int j = 0; j < 4; j++) acc2[f][j] = 0.f;
#pragma unroll
        for (int ks = 0; ks < 4; ks++) {
            uint32_t Ah[4], Al[4];
            ldsm4(Ah, aG3 + ks * 32);
            ldsm4(Al, aG3 + PL + ks * 32);
#pragma unroll
            for (int f2 = 0; f2 < 2; f2++) {
                uint32_t Bh[4], Bl[4];
                ldsm4t(Bh, bG4 + f2 * 32 + ks * 16 * RSB);
                ldsm4t(Bl, bG4 + PL + f2 * 32 + ks * 16 * RSB);
                mma3(acc2[f2 * 2],     Ah, Al, Bh[0], Bh[1], Bl[0], Bl[1]);
                mma3(acc2[f2 * 2 + 1], Ah, Al, Bh[2], Bh[3], Bl[2], Bl[3]);
            }
        }

        // ---- epilogue4: scale by 0.1/den; partial row stats -> PD ----
        {
            float s0 = 0.1f / fmaxf(DEN[tr] + DEN[64 + tr], DEN_EPS);
            float s1 = 0.1f / fmaxf(DEN[tr + 8] + DEN[64 + tr + 8], DEN_EPS);
            float sA = 0.f, ssA = 0.f, sB = 0.f, ssB = 0.f;
#pragma unroll
            for (int f = 0; f < 4; f++) {
                acc2[f][0] *= s0; acc2[f][1] *= s0;
                acc2[f][2] *= s1; acc2[f][3] *= s1;
                sA += acc2[f][0] + acc2[f][1];
                ssA += acc2[f][0] * acc2[f][0] + acc2[f][1] * acc2[f][1];
                sB += acc2[f][2] + acc2[f][3];
                ssB += acc2[f][2] * acc2[f][2] + acc2[f][3] * acc2[f][3];
            }
            sA = qred(sA); ssA = qred(ssA);
            sB = qred(sB); ssB = qred(ssB);
            if ((lane & 3) == 0) {
                PD[nh * 128 + tr] = make_float2(sA, ssA);
                PD[nh * 128 + tr + 8] = make_float2(sB, ssB);
            }
        }
        PAIRBAR();   // B4

        // ---- final LN from registers; direct gmem store ----
        {
            float2 a0 = PD[tr],     b0 = PD[128 + tr];
            float2 a1 = PD[tr + 8], b1 = PD[128 + tr + 8];
            float muA = (a0.x + b0.x) * (1.f / 64.f);
            float rsdA = rsqrtf((a0.y + b0.y) * (1.f / 64.f) - muA * muA + LN_EPS);
            float muB = (a1.x + b1.x) * (1.f / 64.f);
            float rsdB = rsqrtf((a1.y + b1.y) * (1.f / 64.f) - muB * muB + LN_EPS);
            float* o0 = out + ((size_t)(bh * TV + t0 + tr)) * 64;
            float* o1 = out + ((size_t)(bh * TV + t0 + tr + 8)) * 64;
#pragma unroll
            for (int f = 0; f < 4; f++) {
                int c = nh * 32 + f * 8 + qk;
                float g0 = GB[c], g1 = GB[c + 1];
                float be0 = GB[64 + c], be1 = GB[64 + c + 1];
                *(float2*)(o0 + c) = make_float2((acc2[f][0] - muA) * rsdA * g0 + be0,
                                                 (acc2[f][1] - muA) * rsdA * g1 + be1);
                *(float2*)(o1 + c) = make_float2((acc2[f][2] - muB) * rsdB * g0 + be0,
                                                 (acc2[f][3] - muB) * rsdB * g1 + be1);
            }
        }
    }
#undef PAIRBAR
}

// ---------------------------------------------------------------------------
extern "C" void kernel_launch(void* const* d_in, const int* in_sizes, int n_in,
                              void* d_out, int out_size)
{
    const float* q     = (const float*)d_in[0];
    const float* k     = (const float*)d_in[1];
    const float* v     = (const float*)d_in[2];
    const float* proj  = (const float*)d_in[3];
    const float* gamma = (const float*)d_in[4];
    const float* beta  = (const float*)d_in[5];
    float* out = (float*)d_out;

    cudaFuncSetAttribute(fa_pass1, cudaFuncAttributeMaxDynamicSharedMemorySize, P1_BYTES);
    cudaFuncSetAttribute(fa_pass2, cudaFuncAttributeMaxDynamicSharedMemorySize, P2_BYTES);

    fa_setup<<<1, 256>>>(proj);
    fa_pass1<<<dim3(16, BHV), 256, P1_BYTES>>>(k, v, gamma, beta);
    fa_reduce<<<128, 256>>>();
    fa_pass2<<<dim3(16, BHV), 256, P2_BYTES>>>(q, gamma, beta, out);
}

// round 13
// speedup vs baseline: 1.0789x; 1.0789x over previous
#include <cuda_runtime.h>
#include <cuda_bf16.h>
#include <cstdint>

#define TV 8192
#define BHV 32
#define LN_EPS 1e-5f
#define DEN_EPS 1e-6f
#define RSB 144     // plane row stride bytes (72 bf16)
#define PL  9216    // hi->lo plane delta, bytes
#define TPC 8       // 64-token tiles per CTA

// Scratch (allocation-free)
__device__ uint32_t g_kp[(size_t)BHV * TV * 32];            // 32 MB kp 2xbf16 [bh][t][m/2]
__device__ float    g_part[(size_t)BHV * 16 * 4096];        // 8 MB partial kv
__device__ __align__(16) uint32_t g_pjh[2304];              // packed proj plane [m][n]
__device__ __align__(16) uint32_t g_kvh[(size_t)BHV * 2304];
__device__ __align__(16) uint32_t g_kvl[(size_t)BHV * 2304];

// ---------------- helpers ----------------
__device__ __forceinline__ uint32_t smem_u32(const void* p) {
    uint32_t a;
    asm("{ .reg .u64 t; cvta.to.shared.u64 t, %1; cvt.u32.u64 %0, t; }" : "=r"(a) : "l"(p));
    return a;
}
__device__ __forceinline__ float featexp(float x) {
    return __expf(fminf(fmaxf(x, -15.f), 15.f)) * 0.1f;
}
__device__ __forceinline__ float qred(float v) {
    v += __shfl_xor_sync(0xffffffffu, v, 1);
    v += __shfl_xor_sync(0xffffffffu, v, 2);
    return v;
}
__device__ __forceinline__ uint32_t pack2(float x, float y) {
    __nv_bfloat162 b = __floats2bfloat162_rn(x, y);
    return *(uint32_t*)&b;
}
__device__ __forceinline__ float2 unpk2(uint32_t p) {
    __nv_bfloat162 b = *(__nv_bfloat162*)&p;
    return make_float2(__bfloat162float(b.x), __bfloat162float(b.y));
}
__device__ __forceinline__ void packhl2(float a, float b, uint32_t& hi, uint32_t& lo) {
    __nv_bfloat16 ha = __float2bfloat16_rn(a), hb = __float2bfloat16_rn(b);
    __nv_bfloat16 la = __float2bfloat16_rn(a - __bfloat162float(ha));
    __nv_bfloat16 lb = __float2bfloat16_rn(b - __bfloat162float(hb));
    hi = (uint32_t)__bfloat16_as_ushort(ha) | ((uint32_t)__bfloat16_as_ushort(hb) << 16);
    lo = (uint32_t)__bfloat16_as_ushort(la) | ((uint32_t)__bfloat16_as_ushort(lb) << 16);
}
__device__ __forceinline__ void ldsm4(uint32_t* r, uint32_t a) {
    asm volatile("ldmatrix.sync.aligned.m8n8.x4.shared.b16 {%0,%1,%2,%3}, [%4];"
        : "=r"(r[0]), "=r"(r[1]), "=r"(r[2]), "=r"(r[3]) : "r"(a));
}
__device__ __forceinline__ void ldsm4t(uint32_t* r, uint32_t a) {
    asm volatile("ldmatrix.sync.aligned.m8n8.x4.trans.shared.b16 {%0,%1,%2,%3}, [%4];"
        : "=r"(r[0]), "=r"(r[1]), "=r"(r[2]), "=r"(r[3]) : "r"(a));
}
__device__ __forceinline__ void mma_bf16(float* c, const uint32_t* a, uint32_t b0, uint32_t b1) {
    asm("mma.sync.aligned.m16n8k16.row.col.f32.bf16.bf16.f32 "
        "{%0,%1,%2,%3},{%4,%5,%6,%7},{%8,%9},{%0,%1,%2,%3};"
        : "+f"(c[0]), "+f"(c[1]), "+f"(c[2]), "+f"(c[3])
        : "r"(a[0]), "r"(a[1]), "r"(a[2]), "r"(a[3]), "r"(b0), "r"(b1));
}
__device__ __forceinline__ void mma3(float* c, const uint32_t* Ah, const uint32_t* Al,
                                     uint32_t bh0, uint32_t bh1, uint32_t bl0, uint32_t bl1) {
    mma_bf16(c, Ah, bh0, bh1);
    mma_bf16(c, Ah, bl0, bl1);
    mma_bf16(c, Al, bh0, bh1);
}
__device__ __forceinline__ void ln16(float* x, const float* GB, int c0) {
    float s = 0.f, ss = 0.f;
#pragma unroll
    for (int j = 0; j < 16; j++) { s += x[j]; ss += x[j] * x[j]; }
    s = qred(s); ss = qred(ss);
    float mu = s * (1.f / 64.f);
    float rstd = rsqrtf(ss * (1.f / 64.f) - mu * mu + LN_EPS);
#pragma unroll
    for (int j = 0; j < 16; j++)
        x[j] = (x[j] - mu) * rstd * GB[c0 + j] + GB[64 + c0 + j];
}

// pass1 byte offsets (EXACT R10/R11)
#define P1_KN  0
#define P1_KPH 9216
#define P1_KPL 18432
#define P1_PJ  27648
#define P1_VTH 36864
#define P1_VTL 46080
#define P1_GB  55296
#define P1_BYTES 55808
// pass2 byte offsets (R11 + 8KB kp staging)
#define P2_QNH 0       // QN single plane, overlaid by qp-hi
#define P2_QPL 9216    // qp-lo
#define P2_PJ  18432
#define P2_KVH 27648
#define P2_KVL 36864
#define P2_DEN 46080
#define P2_PD  46592   // 256 x float2
#define P2_GB  48640
#define P2_KPS 49152   // kp staging: 64 rows x 128B = 8KB (pair-private bands)
#define P2_BYTES 57344

// ---------------------------------------------------------------------------
extern "C" __global__ void fa_setup(const float* __restrict__ proj)
{
    const int tid = threadIdx.x;
    for (int i = tid; i < 2048; i += 256) {
        int m = i & 63, nw = i >> 6;
        g_pjh[m * 36 + nw] = pack2(proj[(2 * nw) * 64 + m], proj[(2 * nw + 1) * 64 + m]);
    }
}

// ---------------------------------------------------------------------------
// Pass 1: EXACT R11 (proven). CTA = 512 tokens, 2 syncs per tile.
// ---------------------------------------------------------------------------
extern "C" __global__ void __launch_bounds__(256, 4) fa_pass1(
    const float* __restrict__ k, const float* __restrict__ v,
    const float* __restrict__ gamma, const float* __restrict__ beta)
{
    extern __shared__ char sm[];
    const uint32_t sb = smem_u32(sm);
    float* GB = (float*)(sm + P1_GB);

    const int tid = threadIdx.x, lane = tid & 31, wid = tid >> 5;
    const int bh = blockIdx.y, bx = blockIdx.x;
    const int t = tid >> 2, c0 = (tid & 3) * 16;

    if (tid < 64) GB[tid] = gamma[tid];
    else if (tid < 128) GB[tid] = beta[tid - 64];
    {
        const uint4* src = (const uint4*)g_pjh;
        uint4* dst = (uint4*)(sm + P1_PJ);
        for (int i = tid; i < 576; i += 256) dst[i] = src[i];
    }
    __syncthreads();

    const int r = lane >> 2, qk = (lane & 3) * 2;
    const int mb = wid & 3, nh = wid >> 2;
    const int tr = mb * 16 + r;
    const int l7 = lane & 7, l8 = (lane >> 3) & 1, l16 = (lane >> 4) & 1;

    const uint32_t aG1 = sb + P1_KN + (mb * 16 + l7 + l8 * 8) * RSB + l16 * 16;
    const uint32_t bG1 = sb + P1_PJ + (nh * 32 + l7 + l16 * 8) * RSB + l8 * 16;
    const uint32_t aG2 = sb + P1_KPH + (l7 + l16 * 8) * RSB + (mb * 16 + l8 * 8) * 2;
    const uint32_t bG2 = sb + P1_VTH + (l7 + l8 * 8) * RSB + (nh * 32 + l16 * 8) * 2;

    float acc2[4][4];
#pragma unroll
    for (int f = 0; f < 4; f++)
#pragma unroll
        for (int j = 0; j < 4; j++) acc2[f][j] = 0.f;

    for (int it = 0; it < TPC; ++it) {
        const int t0 = (bx * TPC + it) * 64;
        const float* kr = k + ((size_t)(bh * TV + t0 + t)) * 64 + c0;
        const float* vr = v + ((size_t)(bh * TV + t0 + t)) * 64 + c0;

        // ---- Phase 1: LN(k)+L2 -> KN; L2-prefetch v ----
        {
            asm volatile("prefetch.global.L2 [%0];" :: "l"(vr));
            float xk[16];
#pragma unroll
            for (int i = 0; i < 4; i++) *(float4*)(xk + 4 * i) = *(const float4*)(kr + 4 * i);
            ln16(xk, GB, c0);
            float n2 = 0.f;
#pragma unroll
            for (int j = 0; j < 16; j++) n2 += xk[j] * xk[j];
            n2 = qred(n2);
            float inv = 1.f / fmaxf(sqrtf(n2), 1e-12f);
#pragma unroll
            for (int jj = 0; jj < 8; jj++)
                *(uint32_t*)(sm + P1_KN + t * RSB + (c0 + 2 * jj) * 2) =
                    pack2(xk[2 * jj] * inv, xk[2 * jj + 1] * inv);
        }
        __syncthreads();   // S1

        // ---- Phase 2: GEMM1 single-bf16 ----
        float acc[4][4];
#pragma unroll
        for (int f = 0; f < 4; f++)
#pragma unroll
            for (int j = 0; j < 4; j++) acc[f][j] = 0.f;
#pragma unroll
        for (int ks = 0; ks < 4; ks++) {
            uint32_t Ah[4];
            ldsm4(Ah, aG1 + ks * 32);
#pragma unroll
            for (int f2 = 0; f2 < 2; f2++) {
                uint32_t Bh[4];
                ldsm4(Bh, bG1 + f2 * 16 * RSB + ks * 32);
                mma_bf16(acc[f2 * 2],     Ah, Bh[0], Bh[1]);
                mma_bf16(acc[f2 * 2 + 1], Ah, Bh[2], Bh[3]);
            }
        }

        // ---- Phase 3: kp = featexp(D1) -> g_kp + KP hi/lo planes ----
        {
            uint32_t* gkp = g_kp + ((size_t)bh * TV + t0) * 32;
#pragma unroll
            for (int f = 0; f < 4; f++) {
                float x0 = featexp(acc[f][0]), x1 = featexp(acc[f][1]);
                float x2 = featexp(acc[f][2]), x3 = featexp(acc[f][3]);
                int c = nh * 32 + f * 8 + qk;
                gkp[tr * 32 + (c >> 1)] = pack2(x0, x1);
                gkp[(tr + 8) * 32 + (c >> 1)] = pack2(x2, x3);
                uint32_t hi, lo;
                packhl2(x0, x1, hi, lo);
                *(uint32_t*)(sm + P1_KPH + tr * RSB + c * 2) = hi;
                *(uint32_t*)(sm + P1_KPL + tr * RSB + c * 2) = lo;
                packhl2(x2, x3, hi, lo);
                *(uint32_t*)(sm + P1_KPH + (tr + 8) * RSB + c * 2) = hi;
                *(uint32_t*)(sm + P1_KPL + (tr + 8) * RSB + c * 2) = lo;
            }
        }

        // ---- Phase 4: LN(v) -> VT hi/lo ----
        {
            float xv[16];
#pragma unroll
            for (int i = 0; i < 4; i++) *(float4*)(xv + 4 * i) = *(const float4*)(vr + 4 * i);
            ln16(xv, GB, c0);
#pragma unroll
            for (int jj = 0; jj < 8; jj++) {
                uint32_t hi, lo;
                packhl2(xv[2 * jj], xv[2 * jj + 1], hi, lo);
                *(uint32_t*)(sm + P1_VTH + t * RSB + (c0 + 2 * jj) * 2) = hi;
                *(uint32_t*)(sm + P1_VTL + t * RSB + (c0 + 2 * jj) * 2) = lo;
            }
        }
        __syncthreads();   // S2

        // ---- Phase 5: GEMM2 3-term ----
#pragma unroll
        for (int ks = 0; ks < 4; ks++) {
            uint32_t Ah[4], Al[4];
            ldsm4t(Ah, aG2 + ks * 16 * RSB);
            ldsm4t(Al, aG2 + PL + ks * 16 * RSB);
#pragma unroll
            for (int f2 = 0; f2 < 2; f2++) {
                uint32_t Bh[4], Bl[4];
                ldsm4t(Bh, bG2 + f2 * 32 + ks * 16 * RSB);
                ldsm4t(Bl, bG2 + PL + f2 * 32 + ks * 16 * RSB);
                mma3(acc2[f2 * 2],     Ah, Al, Bh[0], Bh[1], Bl[0], Bl[1]);
                mma3(acc2[f2 * 2 + 1], Ah, Al, Bh[2], Bh[3], Bl[2], Bl[3]);
            }
        }
    }

    float* gp = g_part + (size_t)(bh * 16 + bx) * 4096;
#pragma unroll
    for (int f = 0; f < 4; f++) {
        int n = nh * 32 + f * 8 + qk;
        *(float2*)(gp + tr * 64 + n) = make_float2(acc2[f][0], acc2[f][1]);
        *(float2*)(gp + (tr + 8) * 64 + n) = make_float2(acc2[f][2], acc2[f][3]);
    }
}

// ---------------------------------------------------------------------------
extern "C" __global__ void __launch_bounds__(256) fa_reduce()
{
    const int tid = blockIdx.x * 256 + threadIdx.x;
    const int bh = tid >> 10, e4 = tid & 1023;
    const float4* p = (const float4*)(g_part + (size_t)bh * 16 * 4096) + e4;
    float4 s = make_float4(0.f, 0.f, 0.f, 0.f);
#pragma unroll
    for (int c = 0; c < 16; ++c) {
        float4 a = p[(size_t)c * 1024];
        s.x += a.x; s.y += a.y; s.z += a.z; s.w += a.w;
    }
    s.x *= 0.1f; s.y *= 0.1f; s.z *= 0.1f; s.w *= 0.1f;
    const int m = e4 >> 4, n0 = (e4 & 15) * 4;
    const int base = bh * 2304 + m * 36 + (n0 >> 1);
    uint32_t hi, lo;
    packhl2(s.x, s.y, hi, lo);
    g_kvh[base] = hi; g_kvl[base] = lo;
    packhl2(s.z, s.w, hi, lo);
    g_kvh[base + 1] = hi; g_kvl[base + 1] = lo;
}

// ---------------------------------------------------------------------------
// Pass 2: R11 pairwise structure + cp.async kp staging (pair-private bands).
// ---------------------------------------------------------------------------
extern "C" __global__ void __launch_bounds__(256, 4) fa_pass2(
    const float* __restrict__ q, const float* __restrict__ gamma,
    const float* __restrict__ beta, float* __restrict__ out)
{
    extern __shared__ char sm[];
    const uint32_t sb = smem_u32(sm);
    float*  DEN = (float*)(sm + P2_DEN);
    float2* PD  = (float2*)(sm + P2_PD);
    float*  GB  = (float*)(sm + P2_GB);

    const int tid = threadIdx.x, lane = tid & 31, wid = tid >> 5;
    const int bh = blockIdx.y, bx = blockIdx.x;
    const int mb = wid & 3, nh = wid >> 2;
    const int t = mb * 16 + nh * 8 + (lane >> 2);
    const int c0 = (lane & 3) * 16;

    if (tid < 64) GB[tid] = gamma[tid];
    else if (tid < 128) GB[tid] = beta[tid - 64];
    {
        const uint4* src = (const uint4*)g_pjh;
        uint4* dst = (uint4*)(sm + P2_PJ);
        for (int i = tid; i < 576; i += 256) dst[i] = src[i];
        const uint4* kh = (const uint4*)(g_kvh + bh * 2304);
        const uint4* kl = (const uint4*)(g_kvl + bh * 2304);
        uint4* dh = (uint4*)(sm + P2_KVH);
        uint4* dl = (uint4*)(sm + P2_KVL);
        for (int i = tid; i < 576; i += 256) { dh[i] = kh[i]; dl[i] = kl[i]; }
    }
    __syncthreads();   // prologue

    const int r = lane >> 2, qk = (lane & 3) * 2;
    const int tr = mb * 16 + r;
    const int l7 = lane & 7, l8 = (lane >> 3) & 1, l16 = (lane >> 4) & 1;

    const uint32_t aG3 = sb + P2_QNH + (mb * 16 + l7 + l8 * 8) * RSB + l16 * 16;
    const uint32_t bG3 = sb + P2_PJ + (nh * 32 + l7 + l16 * 8) * RSB + l8 * 16;
    const uint32_t bG4 = sb + P2_KVH + (l7 + l8 * 8) * RSB + (nh * 32 + l16 * 8) * 2;

    // kp staging addresses (pair-private: rows mb*16..mb*16+15)
    const int cidx = (nh * 32 + lane) * 2;                 // 2 chunks of 16B per thread
    const uint32_t kps_dst = sb + P2_KPS + (mb * 16 + (cidx >> 3)) * 128 + (cidx & 7) * 16;
    const size_t   kps_soff = (size_t)(mb * 16 + (cidx >> 3)) * 128 + (cidx & 7) * 16;

#define PAIRBAR() asm volatile("bar.sync %0, 64;" :: "r"(mb + 1) : "memory")

    for (int it = 0; it < TPC; ++it) {
        const int t0 = (bx * TPC + it) * 64;
        float x[16];

        // ---- stage this tile's kp band via cp.async (no registers held) ----
        {
            const char* src = (const char*)(g_kp + ((size_t)bh * TV + t0) * 32) + kps_soff;
            asm volatile("cp.async.ca.shared.global [%0], [%1], 16;"
                         :: "r"(kps_dst), "l"(src) : "memory");
            asm volatile("cp.async.ca.shared.global [%0], [%1], 16;"
                         :: "r"(kps_dst + 16), "l"(src + 16) : "memory");
            asm volatile("cp.async.commit_group;" ::: "memory");
        }

        // ---- LN + L2 of q -> QN rows of this pair ----
        {
            const float* qr = q + ((size_t)(bh * TV + t0 + t)) * 64 + c0;
#pragma unroll
            for (int i = 0; i < 4; i++) *(float4*)(x + 4 * i) = *(const float4*)(qr + 4 * i);
            ln16(x, GB, c0);
            float n2 = 0.f;
#pragma unroll
            for (int j = 0; j < 16; j++) n2 += x[j] * x[j];
            n2 = qred(n2);
            float inv = 1.f / fmaxf(sqrtf(n2), 1e-12f);
#pragma unroll
            for (int jj = 0; jj < 8; jj++)
                *(uint32_t*)(sm + P2_QNH + t * RSB + (c0 + 2 * jj) * 2) =
                    pack2(x[2 * jj] * inv, x[2 * jj + 1] * inv);
        }
        PAIRBAR();   // B1

        // ---- GEMM3 single-bf16: D3[t][m] = QN @ PJ^T ----
        float acc[4][4];
#pragma unroll
        for (int f = 0; f < 4; f++)
#pragma unroll
            for (int j = 0; j < 4; j++) acc[f][j] = 0.f;
#pragma unroll
        for (int ks = 0; ks < 4; ks++) {
            uint32_t Ah[4];
            ldsm4(Ah, aG3 + ks * 32);
#pragma unroll
            for (int f2 = 0; f2 < 2; f2++) {
                uint32_t Bh[4];
                ldsm4(Bh, bG3 + f2 * 16 * RSB + ks * 32);
                mma_bf16(acc[f2 * 2],     Ah, Bh[0], Bh[1]);
                mma_bf16(acc[f2 * 2 + 1], Ah, Bh[2], Bh[3]);
            }
        }
        asm volatile("cp.async.wait_group 0;" ::: "memory");   // own copies done
        PAIRBAR();   // B2: partner's copies + QN reads done

        // ---- qp = featexp(D3) -> planes; denom vs staged kp (LDS) ----
        {
            float den0 = 0.f, den1 = 0.f;
#pragma unroll
            for (int f = 0; f < 4; f++) {
                float x0 = featexp(acc[f][0]), x1 = featexp(acc[f][1]);
                float x2 = featexp(acc[f][2]), x3 = featexp(acc[f][3]);
                int c = nh * 32 + f * 8 + qk;
                uint32_t hi, lo;
                packhl2(x0, x1, hi, lo);
                *(uint32_t*)(sm + P2_QNH + tr * RSB + c * 2) = hi;
                *(uint32_t*)(sm + P2_QPL + tr * RSB + c * 2) = lo;
                packhl2(x2, x3, hi, lo);
                *(uint32_t*)(sm + P2_QNH + (tr + 8) * RSB + c * 2) = hi;
                *(uint32_t*)(sm + P2_QPL + (tr + 8) * RSB + c * 2) = lo;
                float2 k0 = unpk2(*(const uint32_t*)(sm + P2_KPS + tr * 128 + (c >> 1) * 4));
                float2 k1 = unpk2(*(const uint32_t*)(sm + P2_KPS + (tr + 8) * 128 + (c >> 1) * 4));
                den0 += x0 * k0.x + x1 * k0.y;
                den1 += x2 * k1.x + x3 * k1.y;
            }
            den0 = qred(den0);
            den1 = qred(den1);
            if ((lane & 3) == 0) { DEN[nh * 64 + tr] = den0; DEN[nh * 64 + tr + 8] = den1; }
        }
        PAIRBAR();   // B3

        // ---- GEMM4 3-term: D4[t][n] = qp @ kv ----
        float acc2[4][4];
#pragma unroll
        for (int f = 0; f < 4; f++)
#pragma unroll
            for (int j = 0; j < 4; j++) acc2[f][j] = 0.f;
#pragma unroll
        for (int ks = 0; ks < 4; ks++) {
            uint32_t Ah[4], Al[4];
            ldsm4(Ah, aG3 + ks * 32);
            ldsm4(Al, aG3 + PL + ks * 32);
#pragma unroll
            for (int f2 = 0; f2 < 2; f2++) {
                uint32_t Bh[4], Bl[4];
                ldsm4t(Bh, bG4 + f2 * 32 + ks * 16 * RSB);
                ldsm4t(Bl, bG4 + PL + f2 * 32 + ks * 16 * RSB);
                mma3(acc2[f2 * 2],     Ah, Al, Bh[0], Bh[1], Bl[0], Bl[1]);
                mma3(acc2[f2 * 2 + 1], Ah, Al, Bh[2], Bh[3], Bl[2], Bl[3]);
            }
        }

        // ---- epilogue4: scale by 0.1/den; partial row stats -> PD ----
        {
            float s0 = 0.1f / fmaxf(DEN[tr] + DEN[64 + tr], DEN_EPS);
            float s1 = 0.1f / fmaxf(DEN[tr + 8] + DEN[64 + tr + 8], DEN_EPS);
            float sA = 0.f, ssA = 0.f, sB = 0.f, ssB = 0.f;
#pragma unroll
            for (int f = 0; f < 4; f++) {
                acc2[f][0] *= s0; acc2[f][1] *= s0;
                acc2[f][2] *= s1; acc2[f][3] *= s1;
                sA += acc2[f][0] + acc2[f][1];
                ssA += acc2[f][0] * acc2[f][0] + acc2[f][1] * acc2[f][1];
                sB += acc2[f][2] + acc2[f][3];
                ssB += acc2[f][2] * acc2[f][2] + acc2[f][3] * acc2[f][3];
            }
            sA = qred(sA); ssA = qred(ssA);
            sB = qred(sB); ssB = qred(ssB);
            if ((lane & 3) == 0) {
                PD[nh * 128 + tr] = make_float2(sA, ssA);
                PD[nh * 128 + tr + 8] = make_float2(sB, ssB);
            }
        }
        PAIRBAR();   // B4: PD ready; GEMM4/staging reads done before next iter

        // ---- final LN from registers; direct gmem store ----
        {
            float2 a0 = PD[tr],     b0 = PD[128 + tr];
            float2 a1 = PD[tr + 8], b1 = PD[128 + tr + 8];
            float muA = (a0.x + b0.x) * (1.f / 64.f);
            float rsdA = rsqrtf((a0.y + b0.y) * (1.f / 64.f) - muA * muA + LN_EPS);
            float muB = (a1.x + b1.x) * (1.f / 64.f);
            float rsdB = rsqrtf((a1.y + b1.y) * (1.f / 64.f) - muB * muB + LN_EPS);
            float* o0 = out + ((size_t)(bh * TV + t0 + tr)) * 64;
            float* o1 = out + ((size_t)(bh * TV + t0 + tr + 8)) * 64;
#pragma unroll
            for (int f = 0; f < 4; f++) {
                int c = nh * 32 + f * 8 + qk;
                float g0 = GB[c], g1 = GB[c + 1];
                float be0 = GB[64 + c], be1 = GB[64 + c + 1];
                *(float2*)(o0 + c) = make_float2((acc2[f][0] - muA) * rsdA * g0 + be0,
                                                 (acc2[f][1] - muA) * rsdA * g1 + be1);
                *(float2*)(o1 + c) = make_float2((acc2[f][2] - muB) * rsdB * g0 + be0,
                                                 (acc2[f][3] - muB) * rsdB * g1 + be1);
            }
        }
    }
#undef PAIRBAR
}

// ---------------------------------------------------------------------------
extern "C" void kernel_launch(void* const* d_in, const int* in_sizes, int n_in,
                              void* d_out, int out_size)
{
    const float* q     = (const float*)d_in[0];
    const float* k     = (const float*)d_in[1];
    const float* v     = (const float*)d_in[2];
    const float* proj  = (const float*)d_in[3];
    const float* gamma = (const float*)d_in[4];
    const float* beta  = (const float*)d_in[5];
    float* out = (float*)d_out;

    cudaFuncSetAttribute(fa_pass1, cudaFuncAttributeMaxDynamicSharedMemorySize, P1_BYTES);
    cudaFuncSetAttribute(fa_pass2, cudaFuncAttributeMaxDynamicSharedMemorySize, P2_BYTES);

    fa_setup<<<1, 256>>>(proj);
    fa_pass1<<<dim3(16, BHV), 256, P1_BYTES>>>(k, v, gamma, beta);
    fa_reduce<<<128, 256>>>();
    fa_pass2<<<dim3(16, BHV), 256, P2_BYTES>>>(q, gamma, beta, out);
}

// round 14
// speedup vs baseline: 1.0847x; 1.0054x over previous
#include <cuda_runtime.h>
#include <cuda_bf16.h>
#include <cstdint>

#define TV 8192
#define BHV 32
#define LN_EPS 1e-5f
#define DEN_EPS 1e-6f
#define RSB 144     // plane row stride bytes (72 bf16)
#define PL  9216    // hi->lo plane delta, bytes
#define TPC 8       // 64-token tiles per CTA

// Scratch (allocation-free)
__device__ uint32_t g_kp[(size_t)BHV * TV * 32];            // 32 MB kp 2xbf16 [bh][t][m/2]
__device__ float    g_part[(size_t)BHV * 16 * 4096];        // 8 MB partial kv
__device__ __align__(16) uint32_t g_pjh[2304];              // packed proj plane [m][n]
__device__ __align__(16) uint32_t g_kvh[(size_t)BHV * 2304];
__device__ __align__(16) uint32_t g_kvl[(size_t)BHV * 2304];

// ---------------- helpers ----------------
__device__ __forceinline__ uint32_t smem_u32(const void* p) {
    uint32_t a;
    asm("{ .reg .u64 t; cvta.to.shared.u64 t, %1; cvt.u32.u64 %0, t; }" : "=r"(a) : "l"(p));
    return a;
}
__device__ __forceinline__ float featexp(float x) {
    return __expf(fminf(fmaxf(x, -15.f), 15.f)) * 0.1f;
}
__device__ __forceinline__ float qred(float v) {
    v += __shfl_xor_sync(0xffffffffu, v, 1);
    v += __shfl_xor_sync(0xffffffffu, v, 2);
    return v;
}
__device__ __forceinline__ uint32_t pack2(float x, float y) {
    __nv_bfloat162 b = __floats2bfloat162_rn(x, y);
    return *(uint32_t*)&b;
}
__device__ __forceinline__ float2 unpk2(uint32_t p) {
    __nv_bfloat162 b = *(__nv_bfloat162*)&p;
    return make_float2(__bfloat162float(b.x), __bfloat162float(b.y));
}
__device__ __forceinline__ void packhl2(float a, float b, uint32_t& hi, uint32_t& lo) {
    __nv_bfloat16 ha = __float2bfloat16_rn(a), hb = __float2bfloat16_rn(b);
    __nv_bfloat16 la = __float2bfloat16_rn(a - __bfloat162float(ha));
    __nv_bfloat16 lb = __float2bfloat16_rn(b - __bfloat162float(hb));
    hi = (uint32_t)__bfloat16_as_ushort(ha) | ((uint32_t)__bfloat16_as_ushort(hb) << 16);
    lo = (uint32_t)__bfloat16_as_ushort(la) | ((uint32_t)__bfloat16_as_ushort(lb) << 16);
}
__device__ __forceinline__ void ldsm4(uint32_t* r, uint32_t a) {
    asm volatile("ldmatrix.sync.aligned.m8n8.x4.shared.b16 {%0,%1,%2,%3}, [%4];"
        : "=r"(r[0]), "=r"(r[1]), "=r"(r[2]), "=r"(r[3]) : "r"(a));
}
__device__ __forceinline__ void ldsm4t(uint32_t* r, uint32_t a) {
    asm volatile("ldmatrix.sync.aligned.m8n8.x4.trans.shared.b16 {%0,%1,%2,%3}, [%4];"
        : "=r"(r[0]), "=r"(r[1]), "=r"(r[2]), "=r"(r[3]) : "r"(a));
}
__device__ __forceinline__ void mma_bf16(float* c, const uint32_t* a, uint32_t b0, uint32_t b1) {
    asm("mma.sync.aligned.m16n8k16.row.col.f32.bf16.bf16.f32 "
        "{%0,%1,%2,%3},{%4,%5,%6,%7},{%8,%9},{%0,%1,%2,%3};"
        : "+f"(c[0]), "+f"(c[1]), "+f"(c[2]), "+f"(c[3])
        : "r"(a[0]), "r"(a[1]), "r"(a[2]), "r"(a[3]), "r"(b0), "r"(b1));
}
__device__ __forceinline__ void mma3(float* c, const uint32_t* Ah, const uint32_t* Al,
                                     uint32_t bh0, uint32_t bh1, uint32_t bl0, uint32_t bl1) {
    mma_bf16(c, Ah, bh0, bh1);
    mma_bf16(c, Ah, bl0, bl1);
    mma_bf16(c, Al, bh0, bh1);
}
__device__ __forceinline__ void ln16(float* x, const float* GB, int c0) {
    float s = 0.f, ss = 0.f;
#pragma unroll
    for (int j = 0; j < 16; j++) { s += x[j]; ss += x[j] * x[j]; }
    s = qred(s); ss = qred(ss);
    float mu = s * (1.f / 64.f);
    float rstd = rsqrtf(ss * (1.f / 64.f) - mu * mu + LN_EPS);
#pragma unroll
    for (int j = 0; j < 16; j++)
        x[j] = (x[j] - mu) * rstd * GB[c0 + j] + GB[64 + c0 + j];
}
// pack 16 scaled floats into two uint4 (8 bf16x2 words)
__device__ __forceinline__ void pack16v(const float* x, float sc, uint4& v0, uint4& v1) {
    v0.x = pack2(x[0] * sc, x[1] * sc);   v0.y = pack2(x[2] * sc, x[3] * sc);
    v0.z = pack2(x[4] * sc, x[5] * sc);   v0.w = pack2(x[6] * sc, x[7] * sc);
    v1.x = pack2(x[8] * sc, x[9] * sc);   v1.y = pack2(x[10] * sc, x[11] * sc);
    v1.z = pack2(x[12] * sc, x[13] * sc); v1.w = pack2(x[14] * sc, x[15] * sc);
}
// pack 16 floats into hi/lo uint4 pairs
__device__ __forceinline__ void pack16hl(const float* x, uint4& h0, uint4& h1, uint4& l0, uint4& l1) {
    packhl2(x[0], x[1], h0.x, l0.x);   packhl2(x[2], x[3], h0.y, l0.y);
    packhl2(x[4], x[5], h0.z, l0.z);   packhl2(x[6], x[7], h0.w, l0.w);
    packhl2(x[8], x[9], h1.x, l1.x);   packhl2(x[10], x[11], h1.y, l1.y);
    packhl2(x[12], x[13], h1.z, l1.z); packhl2(x[14], x[15], h1.w, l1.w);
}

// pass1 byte offsets (EXACT R10/R11)
#define P1_KN  0
#define P1_KPH 9216
#define P1_KPL 18432
#define P1_PJ  27648
#define P1_VTH 36864
#define P1_VTL 46080
#define P1_GB  55296
#define P1_BYTES 55808
// pass2 byte offsets (EXACT R9/R10/R11)
#define P2_QNH 0       // QN single plane, overlaid by qp-hi
#define P2_QPL 9216    // qp-lo
#define P2_PJ  18432
#define P2_KVH 27648
#define P2_KVL 36864
#define P2_DEN 46080
#define P2_PD  46592   // 256 x float2
#define P2_GB  48640
#define P2_BYTES 49152

// ---------------------------------------------------------------------------
extern "C" __global__ void fa_setup(const float* __restrict__ proj)
{
    const int tid = threadIdx.x;
    for (int i = tid; i < 2048; i += 256) {
        int m = i & 63, nw = i >> 6;
        g_pjh[m * 36 + nw] = pack2(proj[(2 * nw) * 64 + m], proj[(2 * nw + 1) * 64 + m]);
    }
}

// ---------------------------------------------------------------------------
// Pass 1: R11 structure, LN stores vectorized to STS.128.
// ---------------------------------------------------------------------------
extern "C" __global__ void __launch_bounds__(256, 4) fa_pass1(
    const float* __restrict__ k, const float* __restrict__ v,
    const float* __restrict__ gamma, const float* __restrict__ beta)
{
    extern __shared__ char sm[];
    const uint32_t sb = smem_u32(sm);
    float* GB = (float*)(sm + P1_GB);

    const int tid = threadIdx.x, lane = tid & 31, wid = tid >> 5;
    const int bh = blockIdx.y, bx = blockIdx.x;
    const int t = tid >> 2, c0 = (tid & 3) * 16;

    if (tid < 64) GB[tid] = gamma[tid];
    else if (tid < 128) GB[tid] = beta[tid - 64];
    {
        const uint4* src = (const uint4*)g_pjh;
        uint4* dst = (uint4*)(sm + P1_PJ);
        for (int i = tid; i < 576; i += 256) dst[i] = src[i];
    }
    __syncthreads();

    const int r = lane >> 2, qk = (lane & 3) * 2;
    const int mb = wid & 3, nh = wid >> 2;
    const int tr = mb * 16 + r;
    const int l7 = lane & 7, l8 = (lane >> 3) & 1, l16 = (lane >> 4) & 1;

    const uint32_t aG1 = sb + P1_KN + (mb * 16 + l7 + l8 * 8) * RSB + l16 * 16;
    const uint32_t bG1 = sb + P1_PJ + (nh * 32 + l7 + l16 * 8) * RSB + l8 * 16;
    const uint32_t aG2 = sb + P1_KPH + (l7 + l16 * 8) * RSB + (mb * 16 + l8 * 8) * 2;
    const uint32_t bG2 = sb + P1_VTH + (l7 + l8 * 8) * RSB + (nh * 32 + l16 * 8) * 2;

    // vectorized LN store base (row t, 32B segment at c0)
    char* lnst = sm + (size_t)t * RSB + c0 * 2;

    float acc2[4][4];
#pragma unroll
    for (int f = 0; f < 4; f++)
#pragma unroll
        for (int j = 0; j < 4; j++) acc2[f][j] = 0.f;

    for (int it = 0; it < TPC; ++it) {
        const int t0 = (bx * TPC + it) * 64;
        const float* kr = k + ((size_t)(bh * TV + t0 + t)) * 64 + c0;
        const float* vr = v + ((size_t)(bh * TV + t0 + t)) * 64 + c0;

        // ---- Phase 1: LN(k)+L2 -> KN (STS.128 x2); L2-prefetch v ----
        {
            asm volatile("prefetch.global.L2 [%0];" :: "l"(vr));
            float xk[16];
#pragma unroll
            for (int i = 0; i < 4; i++) *(float4*)(xk + 4 * i) = *(const float4*)(kr + 4 * i);
            ln16(xk, GB, c0);
            float n2 = 0.f;
#pragma unroll
            for (int j = 0; j < 16; j++) n2 += xk[j] * xk[j];
            n2 = qred(n2);
            float inv = 1.f / fmaxf(sqrtf(n2), 1e-12f);
            uint4 v0, v1;
            pack16v(xk, inv, v0, v1);
            *(uint4*)(lnst + P1_KN) = v0;
            *(uint4*)(lnst + P1_KN + 16) = v1;
        }
        __syncthreads();   // S1

        // ---- Phase 2: GEMM1 single-bf16 ----
        float acc[4][4];
#pragma unroll
        for (int f = 0; f < 4; f++)
#pragma unroll
            for (int j = 0; j < 4; j++) acc[f][j] = 0.f;
#pragma unroll
        for (int ks = 0; ks < 4; ks++) {
            uint32_t Ah[4];
            ldsm4(Ah, aG1 + ks * 32);
#pragma unroll
            for (int f2 = 0; f2 < 2; f2++) {
                uint32_t Bh[4];
                ldsm4(Bh, bG1 + f2 * 16 * RSB + ks * 32);
                mma_bf16(acc[f2 * 2],     Ah, Bh[0], Bh[1]);
                mma_bf16(acc[f2 * 2 + 1], Ah, Bh[2], Bh[3]);
            }
        }

        // ---- Phase 3: kp = featexp(D1) -> g_kp + KP hi/lo planes ----
        {
            uint32_t* gkp = g_kp + ((size_t)bh * TV + t0) * 32;
#pragma unroll
            for (int f = 0; f < 4; f++) {
                float x0 = featexp(acc[f][0]), x1 = featexp(acc[f][1]);
                float x2 = featexp(acc[f][2]), x3 = featexp(acc[f][3]);
                int c = nh * 32 + f * 8 + qk;
                gkp[tr * 32 + (c >> 1)] = pack2(x0, x1);
                gkp[(tr + 8) * 32 + (c >> 1)] = pack2(x2, x3);
                uint32_t hi, lo;
                packhl2(x0, x1, hi, lo);
                *(uint32_t*)(sm + P1_KPH + tr * RSB + c * 2) = hi;
                *(uint32_t*)(sm + P1_KPL + tr * RSB + c * 2) = lo;
                packhl2(x2, x3, hi, lo);
                *(uint32_t*)(sm + P1_KPH + (tr + 8) * RSB + c * 2) = hi;
                *(uint32_t*)(sm + P1_KPL + (tr + 8) * RSB + c * 2) = lo;
            }
        }

        // ---- Phase 4: LN(v) -> VT hi/lo (STS.128 x4) ----
        {
            float xv[16];
#pragma unroll
            for (int i = 0; i < 4; i++) *(float4*)(xv + 4 * i) = *(const float4*)(vr + 4 * i);
            ln16(xv, GB, c0);
            uint4 h0, h1, l0, l1;
            pack16hl(xv, h0, h1, l0, l1);
            *(uint4*)(lnst + P1_VTH) = h0;
            *(uint4*)(lnst + P1_VTH + 16) = h1;
            *(uint4*)(lnst + P1_VTL) = l0;
            *(uint4*)(lnst + P1_VTL + 16) = l1;
        }
        __syncthreads();   // S2

        // ---- Phase 5: GEMM2 3-term ----
#pragma unroll
        for (int ks = 0; ks < 4; ks++) {
            uint32_t Ah[4], Al[4];
            ldsm4t(Ah, aG2 + ks * 16 * RSB);
            ldsm4t(Al, aG2 + PL + ks * 16 * RSB);
#pragma unroll
            for (int f2 = 0; f2 < 2; f2++) {
                uint32_t Bh[4], Bl[4];
                ldsm4t(Bh, bG2 + f2 * 32 + ks * 16 * RSB);
                ldsm4t(Bl, bG2 + PL + f2 * 32 + ks * 16 * RSB);
                mma3(acc2[f2 * 2],     Ah, Al, Bh[0], Bh[1], Bl[0], Bl[1]);
                mma3(acc2[f2 * 2 + 1], Ah, Al, Bh[2], Bh[3], Bl[2], Bl[3]);
            }
        }
    }

    float* gp = g_part + (size_t)(bh * 16 + bx) * 4096;
#pragma unroll
    for (int f = 0; f < 4; f++) {
        int n = nh * 32 + f * 8 + qk;
        *(float2*)(gp + tr * 64 + n) = make_float2(acc2[f][0], acc2[f][1]);
        *(float2*)(gp + (tr + 8) * 64 + n) = make_float2(acc2[f][2], acc2[f][3]);
    }
}

// ---------------------------------------------------------------------------
extern "C" __global__ void __launch_bounds__(256) fa_reduce()
{
    const int tid = blockIdx.x * 256 + threadIdx.x;
    const int bh = tid >> 10, e4 = tid & 1023;
    const float4* p = (const float4*)(g_part + (size_t)bh * 16 * 4096) + e4;
    float4 s = make_float4(0.f, 0.f, 0.f, 0.f);
#pragma unroll
    for (int c = 0; c < 16; ++c) {
        float4 a = p[(size_t)c * 1024];
        s.x += a.x; s.y += a.y; s.z += a.z; s.w += a.w;
    }
    s.x *= 0.1f; s.y *= 0.1f; s.z *= 0.1f; s.w *= 0.1f;
    const int m = e4 >> 4, n0 = (e4 & 15) * 4;
    const int base = bh * 2304 + m * 36 + (n0 >> 1);
    uint32_t hi, lo;
    packhl2(s.x, s.y, hi, lo);
    g_kvh[base] = hi; g_kvl[base] = lo;
    packhl2(s.z, s.w, hi, lo);
    g_kvh[base + 1] = hi; g_kvl[base + 1] = lo;
}

// ---------------------------------------------------------------------------
// Pass 2: EXACT R11 structure (pairwise named barriers, direct g_kp LDG),
// LN store vectorized to STS.128 x2.
// ---------------------------------------------------------------------------
extern "C" __global__ void __launch_bounds__(256, 4) fa_pass2(
    const float* __restrict__ q, const float* __restrict__ gamma,
    const float* __restrict__ beta, float* __restrict__ out)
{
    extern __shared__ char sm[];
    const uint32_t sb = smem_u32(sm);
    float*  DEN = (float*)(sm + P2_DEN);
    float2* PD  = (float2*)(sm + P2_PD);
    float*  GB  = (float*)(sm + P2_GB);

    const int tid = threadIdx.x, lane = tid & 31, wid = tid >> 5;
    const int bh = blockIdx.y, bx = blockIdx.x;
    const int mb = wid & 3, nh = wid >> 2;
    const int t = mb * 16 + nh * 8 + (lane >> 2);
    const int c0 = (lane & 3) * 16;

    if (tid < 64) GB[tid] = gamma[tid];
    else if (tid < 128) GB[tid] = beta[tid - 64];
    {
        const uint4* src = (const uint4*)g_pjh;
        uint4* dst = (uint4*)(sm + P2_PJ);
        for (int i = tid; i < 576; i += 256) dst[i] = src[i];
        const uint4* kh = (const uint4*)(g_kvh + bh * 2304);
        const uint4* kl = (const uint4*)(g_kvl + bh * 2304);
        uint4* dh = (uint4*)(sm + P2_KVH);
        uint4* dl = (uint4*)(sm + P2_KVL);
        for (int i = tid; i < 576; i += 256) { dh[i] = kh[i]; dl[i] = kl[i]; }
    }
    __syncthreads();

    const int r = lane >> 2, qk = (lane & 3) * 2;
    const int tr = mb * 16 + r;
    const int l7 = lane & 7, l8 = (lane >> 3) & 1, l16 = (lane >> 4) & 1;

    const uint32_t aG3 = sb + P2_QNH + (mb * 16 + l7 + l8 * 8) * RSB + l16 * 16;
    const uint32_t bG3 = sb + P2_PJ + (nh * 32 + l7 + l16 * 8) * RSB + l8 * 16;
    const uint32_t bG4 = sb + P2_KVH + (l7 + l8 * 8) * RSB + (nh * 32 + l16 * 8) * 2;
    char* lnst = sm + P2_QNH + (size_t)t * RSB + c0 * 2;

#define PAIRBAR() asm volatile("bar.sync %0, 64;" :: "r"(mb + 1) : "memory")

    for (int it = 0; it < TPC; ++it) {
        const int t0 = (bx * TPC + it) * 64;
        float x[16];

        // ---- LN + L2 of q -> QN rows (STS.128 x2) ----
        {
            const float* qr = q + ((size_t)(bh * TV + t0 + t)) * 64 + c0;
#pragma unroll
            for (int i = 0; i < 4; i++) *(float4*)(x + 4 * i) = *(const float4*)(qr + 4 * i);
            ln16(x, GB, c0);
            float n2 = 0.f;
#pragma unroll
            for (int j = 0; j < 16; j++) n2 += x[j] * x[j];
            n2 = qred(n2);
            float inv = 1.f / fmaxf(sqrtf(n2), 1e-12f);
            uint4 v0, v1;
            pack16v(x, inv, v0, v1);
            *(uint4*)(lnst) = v0;
            *(uint4*)(lnst + 16) = v1;
        }
        PAIRBAR();   // B1

        // ---- GEMM3 single-bf16: D3[t][m] = QN @ PJ^T ----
        float acc[4][4];
#pragma unroll
        for (int f = 0; f < 4; f++)
#pragma unroll
            for (int j = 0; j < 4; j++) acc[f][j] = 0.f;
#pragma unroll
        for (int ks = 0; ks < 4; ks++) {
            uint32_t Ah[4];
            ldsm4(Ah, aG3 + ks * 32);
#pragma unroll
            for (int f2 = 0; f2 < 2; f2++) {
                uint32_t Bh[4];
                ldsm4(Bh, bG3 + f2 * 16 * RSB + ks * 32);
                mma_bf16(acc[f2 * 2],     Ah, Bh[0], Bh[1]);
                mma_bf16(acc[f2 * 2 + 1], Ah, Bh[2], Bh[3]);
            }
        }
        PAIRBAR();   // B2

        // ---- qp = featexp(D3) -> planes; denom partials vs g_kp ----
        {
            const uint32_t* gkp = g_kp + ((size_t)bh * TV + t0) * 32;
            float den0 = 0.f, den1 = 0.f;
#pragma unroll
            for (int f = 0; f < 4; f++) {
                float x0 = featexp(acc[f][0]), x1 = featexp(acc[f][1]);
                float x2 = featexp(acc[f][2]), x3 = featexp(acc[f][3]);
                int c = nh * 32 + f * 8 + qk;
                uint32_t hi, lo;
                packhl2(x0, x1, hi, lo);
                *(uint32_t*)(sm + P2_QNH + tr * RSB + c * 2) = hi;
                *(uint32_t*)(sm + P2_QPL + tr * RSB + c * 2) = lo;
                packhl2(x2, x3, hi, lo);
                *(uint32_t*)(sm + P2_QNH + (tr + 8) * RSB + c * 2) = hi;
                *(uint32_t*)(sm + P2_QPL + (tr + 8) * RSB + c * 2) = lo;
                float2 k0 = unpk2(gkp[tr * 32 + (c >> 1)]);
                float2 k1 = unpk2(gkp[(tr + 8) * 32 + (c >> 1)]);
                den0 += x0 * k0.x + x1 * k0.y;
                den1 += x2 * k1.x + x3 * k1.y;
            }
            den0 = qred(den0);
            den1 = qred(den1);
            if ((lane & 3) == 0) { DEN[nh * 64 + tr] = den0; DEN[nh * 64 + tr + 8] = den1; }
        }
        PAIRBAR();   // B3

        // ---- GEMM4 3-term: D4[t][n] = qp @ kv ----
        float acc2[4][4];
#pragma unroll
        for (int f = 0; f < 4; f++)
#pragma unroll
            for (int j = 0; j < 4; j++) acc2[f][j] = 0.f;
#pragma unroll
        for (int ks = 0; ks < 4; ks++) {
            uint32_t Ah[4], Al[4];
            ldsm4(Ah, aG3 + ks * 32);
            ldsm4(Al, aG3 + PL + ks * 32);
#pragma unroll
            for (int f2 = 0; f2 < 2; f2++) {
                uint32_t Bh[4], Bl[4];
                ldsm4t(Bh, bG4 + f2 * 32 + ks * 16 * RSB);
                ldsm4t(Bl, bG4 + PL + f2 * 32 + ks * 16 * RSB);
                mma3(acc2[f2 * 2],     Ah, Al, Bh[0], Bh[1], Bl[0], Bl[1]);
                mma3(acc2[f2 * 2 + 1], Ah, Al, Bh[2], Bh[3], Bl[2], Bl[3]);
            }
        }

        // ---- epilogue4: scale by 0.1/den; partial row stats -> PD ----
        {
            float s0 = 0.1f / fmaxf(DEN[tr] + DEN[64 + tr], DEN_EPS);
            float s1 = 0.1f / fmaxf(DEN[tr + 8] + DEN[64 + tr + 8], DEN_EPS);
            float sA = 0.f, ssA = 0.f, sB = 0.f, ssB = 0.f;
#pragma unroll
            for (int f = 0; f < 4; f++) {
                acc2[f][0] *= s0; acc2[f][1] *= s0;
                acc2[f][2] *= s1; acc2[f][3] *= s1;
                sA += acc2[f][0] + acc2[f][1];
                ssA += acc2[f][0] * acc2[f][0] + acc2[f][1] * acc2[f][1];
                sB += acc2[f][2] + acc2[f][3];
                ssB += acc2[f][2] * acc2[f][2] + acc2[f][3] * acc2[f][3];
            }
            sA = qred(sA); ssA = qred(ssA);
            sB = qred(sB); ssB = qred(ssB);
            if ((lane & 3) == 0) {
                PD[nh * 128 + tr] = make_float2(sA, ssA);
                PD[nh * 128 + tr + 8] = make_float2(sB, ssB);
            }
        }
        PAIRBAR();   // B4

        // ---- final LN from registers; direct gmem store ----
        {
            float2 a0 = PD[tr],     b0 = PD[128 + tr];
            float2 a1 = PD[tr + 8], b1 = PD[128 + tr + 8];
            float muA = (a0.x + b0.x) * (1.f / 64.f);
            float rsdA = rsqrtf((a0.y + b0.y) * (1.f / 64.f) - muA * muA + LN_EPS);
            float muB = (a1.x + b1.x) * (1.f / 64.f);
            float rsdB = rsqrtf((a1.y + b1.y) * (1.f / 64.f) - muB * muB + LN_EPS);
            float* o0 = out + ((size_t)(bh * TV + t0 + tr)) * 64;
            float* o1 = out + ((size_t)(bh * TV + t0 + tr + 8)) * 64;
#pragma unroll
            for (int f = 0; f < 4; f++) {
                int c = nh * 32 + f * 8 + qk;
                float g0 = GB[c], g1 = GB[c + 1];
                float be0 = GB[64 + c], be1 = GB[64 + c + 1];
                *(float2*)(o0 + c) = make_float2((acc2[f][0] - muA) * rsdA * g0 + be0,
                                                 (acc2[f][1] - muA) * rsdA * g1 + be1);
                *(float2*)(o1 + c) = make_float2((acc2[f][2] - muB) * rsdB * g0 + be0,
                                                 (acc2[f][3] - muB) * rsdB * g1 + be1);
            }
        }
    }
#undef PAIRBAR
}

// ---------------------------------------------------------------------------
extern "C" void kernel_launch(void* const* d_in, const int* in_sizes, int n_in,
                              void* d_out, int out_size)
{
    const float* q     = (const float*)d_in[0];
    const float* k     = (const float*)d_in[1];
    const float* v     = (const float*)d_in[2];
    const float* proj  = (const float*)d_in[3];
    const float* gamma = (const float*)d_in[4];
    const float* beta  = (const float*)d_in[5];
    float* out = (float*)d_out;

    cudaFuncSetAttribute(fa_pass1, cudaFuncAttributeMaxDynamicSharedMemorySize, P1_BYTES);
    cudaFuncSetAttribute(fa_pass2, cudaFuncAttributeMaxDynamicSharedMemorySize, P2_BYTES);

    fa_setup<<<1, 256>>>(proj);
    fa_pass1<<<dim3(16, BHV), 256, P1_BYTES>>>(k, v, gamma, beta);
    fa_reduce<<<128, 256>>>();
    fa_pass2<<<dim3(16, BHV), 256, P2_BYTES>>>(q, gamma, beta, out);
}

// round 15
// speedup vs baseline: 1.2580x; 1.1598x over previous
#include <cuda_runtime.h>
#include <cuda_bf16.h>
#include <cuda_fp16.h>
#include <cstdint>

#define TV 8192
#define BHV 32
#define LN_EPS 1e-5f
#define DEN_EPS 1e-6f
#define RSB 144     // plane row stride bytes (72 fp16)
#define TPC 8       // 64-token tiles per CTA

// Scratch (allocation-free)
__device__ uint32_t g_kp[(size_t)BHV * TV * 32];            // 32 MB kp 2xbf16 [bh][t][m/2] (denominator)
__device__ float    g_part[(size_t)BHV * 16 * 4096];        // 8 MB partial kv
__device__ __align__(16) uint32_t g_pjh[2304];              // packed fp16 proj plane [m][n]
__device__ __align__(16) uint32_t g_kvh[(size_t)BHV * 2304];// packed fp16 kv plane per bh

// ---------------- helpers ----------------
__device__ __forceinline__ uint32_t smem_u32(const void* p) {
    uint32_t a;
    asm("{ .reg .u64 t; cvta.to.shared.u64 t, %1; cvt.u32.u64 %0, t; }" : "=r"(a) : "l"(p));
    return a;
}
__device__ __forceinline__ float featexp(float x) {
    return __expf(fminf(fmaxf(x, -15.f), 15.f)) * 0.1f;
}
__device__ __forceinline__ float qred(float v) {
    v += __shfl_xor_sync(0xffffffffu, v, 1);
    v += __shfl_xor_sync(0xffffffffu, v, 2);
    return v;
}
// bf16 pair (for g_kp / denominator only)
__device__ __forceinline__ uint32_t pack2b(float x, float y) {
    __nv_bfloat162 b = __floats2bfloat162_rn(x, y);
    return *(uint32_t*)&b;
}
__device__ __forceinline__ float2 unpk2b(uint32_t p) {
    __nv_bfloat162 b = *(__nv_bfloat162*)&p;
    return make_float2(__bfloat162float(b.x), __bfloat162float(b.y));
}
// fp16 pair (GEMM operands)
__device__ __forceinline__ uint32_t pack2h(float x, float y) {
    __half2 h = __floats2half2_rn(x, y);
    return *(uint32_t*)&h;
}
__device__ __forceinline__ void ldsm4(uint32_t* r, uint32_t a) {
    asm volatile("ldmatrix.sync.aligned.m8n8.x4.shared.b16 {%0,%1,%2,%3}, [%4];"
        : "=r"(r[0]), "=r"(r[1]), "=r"(r[2]), "=r"(r[3]) : "r"(a));
}
__device__ __forceinline__ void ldsm4t(uint32_t* r, uint32_t a) {
    asm volatile("ldmatrix.sync.aligned.m8n8.x4.trans.shared.b16 {%0,%1,%2,%3}, [%4];"
        : "=r"(r[0]), "=r"(r[1]), "=r"(r[2]), "=r"(r[3]) : "r"(a));
}
__device__ __forceinline__ void mma_f16(float* c, const uint32_t* a, uint32_t b0, uint32_t b1) {
    asm("mma.sync.aligned.m16n8k16.row.col.f32.f16.f16.f32 "
        "{%0,%1,%2,%3},{%4,%5,%6,%7},{%8,%9},{%0,%1,%2,%3};"
        : "+f"(c[0]), "+f"(c[1]), "+f"(c[2]), "+f"(c[3])
        : "r"(a[0]), "r"(a[1]), "r"(a[2]), "r"(a[3]), "r"(b0), "r"(b1));
}
__device__ __forceinline__ void ln16(float* x, const float* GB, int c0) {
    float s = 0.f, ss = 0.f;
#pragma unroll
    for (int j = 0; j < 16; j++) { s += x[j]; ss += x[j] * x[j]; }
    s = qred(s); ss = qred(ss);
    float mu = s * (1.f / 64.f);
    float rstd = rsqrtf(ss * (1.f / 64.f) - mu * mu + LN_EPS);
#pragma unroll
    for (int j = 0; j < 16; j++)
        x[j] = (x[j] - mu) * rstd * GB[c0 + j] + GB[64 + c0 + j];
}
// pack 16 scaled floats into two uint4 (8 fp16x2 words)
__device__ __forceinline__ void pack16vh(const float* x, float sc, uint4& v0, uint4& v1) {
    v0.x = pack2h(x[0] * sc, x[1] * sc);   v0.y = pack2h(x[2] * sc, x[3] * sc);
    v0.z = pack2h(x[4] * sc, x[5] * sc);   v0.w = pack2h(x[6] * sc, x[7] * sc);
    v1.x = pack2h(x[8] * sc, x[9] * sc);   v1.y = pack2h(x[10] * sc, x[11] * sc);
    v1.z = pack2h(x[12] * sc, x[13] * sc); v1.w = pack2h(x[14] * sc, x[15] * sc);
}

// pass1 byte offsets (single fp16 planes)
#define P1_KN  0
#define P1_KP  9216
#define P1_PJ  18432
#define P1_VT  27648
#define P1_GB  36864
#define P1_BYTES 37376
// pass2 byte offsets
#define P2_QN  0       // QN plane, overlaid by qp
#define P2_PJ  9216
#define P2_KV  18432
#define P2_DEN 27648
#define P2_PD  28160   // 256 x float2
#define P2_GB  30208
#define P2_BYTES 30720

// ---------------------------------------------------------------------------
extern "C" __global__ void fa_setup(const float* __restrict__ proj)
{
    const int tid = threadIdx.x;
    for (int i = tid; i < 2048; i += 256) {
        int m = i & 63, nw = i >> 6;
        g_pjh[m * 36 + nw] = pack2h(proj[(2 * nw) * 64 + m], proj[(2 * nw + 1) * 64 + m]);
    }
}

// ---------------------------------------------------------------------------
// Pass 1: R11 structure (2 syncs/tile), all GEMM operands single fp16.
// ---------------------------------------------------------------------------
extern "C" __global__ void __launch_bounds__(256, 4) fa_pass1(
    const float* __restrict__ k, const float* __restrict__ v,
    const float* __restrict__ gamma, const float* __restrict__ beta)
{
    extern __shared__ char sm[];
    const uint32_t sb = smem_u32(sm);
    float* GB = (float*)(sm + P1_GB);

    const int tid = threadIdx.x, lane = tid & 31, wid = tid >> 5;
    const int bh = blockIdx.y, bx = blockIdx.x;
    const int t = tid >> 2, c0 = (tid & 3) * 16;

    if (tid < 64) GB[tid] = gamma[tid];
    else if (tid < 128) GB[tid] = beta[tid - 64];
    {
        const uint4* src = (const uint4*)g_pjh;
        uint4* dst = (uint4*)(sm + P1_PJ);
        for (int i = tid; i < 576; i += 256) dst[i] = src[i];
    }
    __syncthreads();

    const int r = lane >> 2, qk = (lane & 3) * 2;
    const int mb = wid & 3, nh = wid >> 2;
    const int tr = mb * 16 + r;
    const int l7 = lane & 7, l8 = (lane >> 3) & 1, l16 = (lane >> 4) & 1;

    const uint32_t aG1 = sb + P1_KN + (mb * 16 + l7 + l8 * 8) * RSB + l16 * 16;
    const uint32_t bG1 = sb + P1_PJ + (nh * 32 + l7 + l16 * 8) * RSB + l8 * 16;
    const uint32_t aG2 = sb + P1_KP + (l7 + l16 * 8) * RSB + (mb * 16 + l8 * 8) * 2;
    const uint32_t bG2 = sb + P1_VT + (l7 + l8 * 8) * RSB + (nh * 32 + l16 * 8) * 2;

    char* lnst = sm + (size_t)t * RSB + c0 * 2;

    float acc2[4][4];
#pragma unroll
    for (int f = 0; f < 4; f++)
#pragma unroll
        for (int j = 0; j < 4; j++) acc2[f][j] = 0.f;

    for (int it = 0; it < TPC; ++it) {
        const int t0 = (bx * TPC + it) * 64;
        const float* kr = k + ((size_t)(bh * TV + t0 + t)) * 64 + c0;
        const float* vr = v + ((size_t)(bh * TV + t0 + t)) * 64 + c0;

        // ---- Phase 1: LN(k)+L2 -> KN (fp16, STS.128 x2); prefetch v ----
        {
            asm volatile("prefetch.global.L2 [%0];" :: "l"(vr));
            float xk[16];
#pragma unroll
            for (int i = 0; i < 4; i++) *(float4*)(xk + 4 * i) = *(const float4*)(kr + 4 * i);
            ln16(xk, GB, c0);
            float n2 = 0.f;
#pragma unroll
            for (int j = 0; j < 16; j++) n2 += xk[j] * xk[j];
            n2 = qred(n2);
            float inv = 1.f / fmaxf(sqrtf(n2), 1e-12f);
            uint4 v0, v1;
            pack16vh(xk, inv, v0, v1);
            *(uint4*)(lnst + P1_KN) = v0;
            *(uint4*)(lnst + P1_KN + 16) = v1;
        }
        __syncthreads();   // S1

        // ---- Phase 2: GEMM1 fp16: D1[t][m] = KN @ PJ^T ----
        float acc[4][4];
#pragma unroll
        for (int f = 0; f < 4; f++)
#pragma unroll
            for (int j = 0; j < 4; j++) acc[f][j] = 0.f;
#pragma unroll
        for (int ks = 0; ks < 4; ks++) {
            uint32_t Ah[4];
            ldsm4(Ah, aG1 + ks * 32);
#pragma unroll
            for (int f2 = 0; f2 < 2; f2++) {
                uint32_t Bh[4];
                ldsm4(Bh, bG1 + f2 * 16 * RSB + ks * 32);
                mma_f16(acc[f2 * 2],     Ah, Bh[0], Bh[1]);
                mma_f16(acc[f2 * 2 + 1], Ah, Bh[2], Bh[3]);
            }
        }

        // ---- Phase 3: kp = featexp(D1) -> g_kp (bf16) + KP plane (fp16) ----
        {
            uint32_t* gkp = g_kp + ((size_t)bh * TV + t0) * 32;
#pragma unroll
            for (int f = 0; f < 4; f++) {
                float x0 = featexp(acc[f][0]), x1 = featexp(acc[f][1]);
                float x2 = featexp(acc[f][2]), x3 = featexp(acc[f][3]);
                int c = nh * 32 + f * 8 + qk;
                gkp[tr * 32 + (c >> 1)] = pack2b(x0, x1);
                gkp[(tr + 8) * 32 + (c >> 1)] = pack2b(x2, x3);
                *(uint32_t*)(sm + P1_KP + tr * RSB + c * 2) = pack2h(x0, x1);
                *(uint32_t*)(sm + P1_KP + (tr + 8) * RSB + c * 2) = pack2h(x2, x3);
            }
        }

        // ---- Phase 4: LN(v) -> VT fp16 (STS.128 x2) ----
        {
            float xv[16];
#pragma unroll
            for (int i = 0; i < 4; i++) *(float4*)(xv + 4 * i) = *(const float4*)(vr + 4 * i);
            ln16(xv, GB, c0);
            uint4 v0, v1;
            pack16vh(xv, 1.f, v0, v1);
            *(uint4*)(lnst + P1_VT) = v0;
            *(uint4*)(lnst + P1_VT + 16) = v1;
        }
        __syncthreads();   // S2

        // ---- Phase 5: GEMM2 fp16: acc2[m][n] += kp^T @ vn ----
#pragma unroll
        for (int ks = 0; ks < 4; ks++) {
            uint32_t Ah[4];
            ldsm4t(Ah, aG2 + ks * 16 * RSB);
#pragma unroll
            for (int f2 = 0; f2 < 2; f2++) {
                uint32_t Bh[4];
                ldsm4t(Bh, bG2 + f2 * 32 + ks * 16 * RSB);
                mma_f16(acc2[f2 * 2],     Ah, Bh[0], Bh[1]);
                mma_f16(acc2[f2 * 2 + 1], Ah, Bh[2], Bh[3]);
            }
        }
    }

    float* gp = g_part + (size_t)(bh * 16 + bx) * 4096;
#pragma unroll
    for (int f = 0; f < 4; f++) {
        int n = nh * 32 + f * 8 + qk;
        *(float2*)(gp + tr * 64 + n) = make_float2(acc2[f][0], acc2[f][1]);
        *(float2*)(gp + (tr + 8) * 64 + n) = make_float2(acc2[f][2], acc2[f][3]);
    }
}

// ---------------------------------------------------------------------------
extern "C" __global__ void __launch_bounds__(256) fa_reduce()
{
    const int tid = blockIdx.x * 256 + threadIdx.x;
    const int bh = tid >> 10, e4 = tid & 1023;
    const float4* p = (const float4*)(g_part + (size_t)bh * 16 * 4096) + e4;
    float4 s = make_float4(0.f, 0.f, 0.f, 0.f);
#pragma unroll
    for (int c = 0; c < 16; ++c) {
        float4 a = p[(size_t)c * 1024];
        s.x += a.x; s.y += a.y; s.z += a.z; s.w += a.w;
    }
    s.x *= 0.1f; s.y *= 0.1f; s.z *= 0.1f; s.w *= 0.1f;
    const int m = e4 >> 4, n0 = (e4 & 15) * 4;
    const int base = bh * 2304 + m * 36 + (n0 >> 1);
    g_kvh[base]     = pack2h(s.x, s.y);
    g_kvh[base + 1] = pack2h(s.z, s.w);
}

// ---------------------------------------------------------------------------
// Pass 2: R11 pairwise structure, single fp16 operands.
// ---------------------------------------------------------------------------
extern "C" __global__ void __launch_bounds__(256, 4) fa_pass2(
    const float* __restrict__ q, const float* __restrict__ gamma,
    const float* __restrict__ beta, float* __restrict__ out)
{
    extern __shared__ char sm[];
    const uint32_t sb = smem_u32(sm);
    float*  DEN = (float*)(sm + P2_DEN);
    float2* PD  = (float2*)(sm + P2_PD);
    float*  GB  = (float*)(sm + P2_GB);

    const int tid = threadIdx.x, lane = tid & 31, wid = tid >> 5;
    const int bh = blockIdx.y, bx = blockIdx.x;
    const int mb = wid & 3, nh = wid >> 2;
    const int t = mb * 16 + nh * 8 + (lane >> 2);
    const int c0 = (lane & 3) * 16;

    if (tid < 64) GB[tid] = gamma[tid];
    else if (tid < 128) GB[tid] = beta[tid - 64];
    {
        const uint4* src = (const uint4*)g_pjh;
        uint4* dst = (uint4*)(sm + P2_PJ);
        for (int i = tid; i < 576; i += 256) dst[i] = src[i];
        const uint4* kh = (const uint4*)(g_kvh + bh * 2304);
        uint4* dh = (uint4*)(sm + P2_KV);
        for (int i = tid; i < 576; i += 256) dh[i] = kh[i];
    }
    __syncthreads();

    const int r = lane >> 2, qk = (lane & 3) * 2;
    const int tr = mb * 16 + r;
    const int l7 = lane & 7, l8 = (lane >> 3) & 1, l16 = (lane >> 4) & 1;

    const uint32_t aG3 = sb + P2_QN + (mb * 16 + l7 + l8 * 8) * RSB + l16 * 16;
    const uint32_t bG3 = sb + P2_PJ + (nh * 32 + l7 + l16 * 8) * RSB + l8 * 16;
    const uint32_t bG4 = sb + P2_KV + (l7 + l8 * 8) * RSB + (nh * 32 + l16 * 8) * 2;
    char* lnst = sm + P2_QN + (size_t)t * RSB + c0 * 2;

#define PAIRBAR() asm volatile("bar.sync %0, 64;" :: "r"(mb + 1) : "memory")

    for (int it = 0; it < TPC; ++it) {
        const int t0 = (bx * TPC + it) * 64;
        float x[16];

        // ---- LN + L2 of q -> QN fp16 (STS.128 x2) ----
        {
            const float* qr = q + ((size_t)(bh * TV + t0 + t)) * 64 + c0;
#pragma unroll
            for (int i = 0; i < 4; i++) *(float4*)(x + 4 * i) = *(const float4*)(qr + 4 * i);
            ln16(x, GB, c0);
            float n2 = 0.f;
#pragma unroll
            for (int j = 0; j < 16; j++) n2 += x[j] * x[j];
            n2 = qred(n2);
            float inv = 1.f / fmaxf(sqrtf(n2), 1e-12f);
            uint4 v0, v1;
            pack16vh(x, inv, v0, v1);
            *(uint4*)(lnst) = v0;
            *(uint4*)(lnst + 16) = v1;
        }
        PAIRBAR();   // B1

        // ---- GEMM3 fp16: D3[t][m] = QN @ PJ^T ----
        float acc[4][4];
#pragma unroll
        for (int f = 0; f < 4; f++)
#pragma unroll
            for (int j = 0; j < 4; j++) acc[f][j] = 0.f;
#pragma unroll
        for (int ks = 0; ks < 4; ks++) {
            uint32_t Ah[4];
            ldsm4(Ah, aG3 + ks * 32);
#pragma unroll
            for (int f2 = 0; f2 < 2; f2++) {
                uint32_t Bh[4];
                ldsm4(Bh, bG3 + f2 * 16 * RSB + ks * 32);
                mma_f16(acc[f2 * 2],     Ah, Bh[0], Bh[1]);
                mma_f16(acc[f2 * 2 + 1], Ah, Bh[2], Bh[3]);
            }
        }
        PAIRBAR();   // B2

        // ---- qp = featexp(D3) -> QN overlay (fp16); denom vs g_kp ----
        {
            const uint32_t* gkp = g_kp + ((size_t)bh * TV + t0) * 32;
            float den0 = 0.f, den1 = 0.f;
#pragma unroll
            for (int f = 0; f < 4; f++) {
                float x0 = featexp(acc[f][0]), x1 = featexp(acc[f][1]);
                float x2 = featexp(acc[f][2]), x3 = featexp(acc[f][3]);
                int c = nh * 32 + f * 8 + qk;
                *(uint32_t*)(sm + P2_QN + tr * RSB + c * 2) = pack2h(x0, x1);
                *(uint32_t*)(sm + P2_QN + (tr + 8) * RSB + c * 2) = pack2h(x2, x3);
                float2 k0 = unpk2b(gkp[tr * 32 + (c >> 1)]);
                float2 k1 = unpk2b(gkp[(tr + 8) * 32 + (c >> 1)]);
                den0 += x0 * k0.x + x1 * k0.y;
                den1 += x2 * k1.x + x3 * k1.y;
            }
            den0 = qred(den0);
            den1 = qred(den1);
            if ((lane & 3) == 0) { DEN[nh * 64 + tr] = den0; DEN[nh * 64 + tr + 8] = den1; }
        }
        PAIRBAR();   // B3

        // ---- GEMM4 fp16: D4[t][n] = qp @ kv ----
        float acc2[4][4];
#pragma unroll
        for (int f = 0; f < 4; f++)
#pragma unroll
            for (int j = 0; j < 4; j++) acc2[f][j] = 0.f;
#pragma unroll
        for (int ks = 0; ks < 4; ks++) {
            uint32_t Ah[4];
            ldsm4(Ah, aG3 + ks * 32);
#pragma unroll
            for (int f2 = 0; f2 < 2; f2++) {
                uint32_t Bh[4];
                ldsm4t(Bh, bG4 + f2 * 32 + ks * 16 * RSB);
                mma_f16(acc2[f2 * 2],     Ah, Bh[0], Bh[1]);
                mma_f16(acc2[f2 * 2 + 1], Ah, Bh[2], Bh[3]);
            }
        }

        // ---- epilogue4: scale by 0.1/den; partial row stats -> PD ----
        {
            float s0 = 0.1f / fmaxf(DEN[tr] + DEN[64 + tr], DEN_EPS);
            float s1 = 0.1f / fmaxf(DEN[tr + 8] + DEN[64 + tr + 8], DEN_EPS);
            float sA = 0.f, ssA = 0.f, sB = 0.f, ssB = 0.f;
#pragma unroll
            for (int f = 0; f < 4; f++) {
                acc2[f][0] *= s0; acc2[f][1] *= s0;
                acc2[f][2] *= s1; acc2[f][3] *= s1;
                sA += acc2[f][0] + acc2[f][1];
                ssA += acc2[f][0] * acc2[f][0] + acc2[f][1] * acc2[f][1];
                sB += acc2[f][2] + acc2[f][3];
                ssB += acc2[f][2] * acc2[f][2] + acc2[f][3] * acc2[f][3];
            }
            sA = qred(sA); ssA = qred(ssA);
            sB = qred(sB); ssB = qred(ssB);
            if ((lane & 3) == 0) {
                PD[nh * 128 + tr] = make_float2(sA, ssA);
                PD[nh * 128 + tr + 8] = make_float2(sB, ssB);
            }
        }
        PAIRBAR();   // B4

        // ---- final LN from registers; direct gmem store ----
        {
            float2 a0 = PD[tr],     b0 = PD[128 + tr];
            float2 a1 = PD[tr + 8], b1 = PD[128 + tr + 8];
            float muA = (a0.x + b0.x) * (1.f / 64.f);
            float rsdA = rsqrtf((a0.y + b0.y) * (1.f / 64.f) - muA * muA + LN_EPS);
            float muB = (a1.x + b1.x) * (1.f / 64.f);
            float rsdB = rsqrtf((a1.y + b1.y) * (1.f / 64.f) - muB * muB + LN_EPS);
            float* o0 = out + ((size_t)(bh * TV + t0 + tr)) * 64;
            float* o1 = out + ((size_t)(bh * TV + t0 + tr + 8)) * 64;
#pragma unroll
            for (int f = 0; f < 4; f++) {
                int c = nh * 32 + f * 8 + qk;
                float g0 = GB[c], g1 = GB[c + 1];
                float be0 = GB[64 + c], be1 = GB[64 + c + 1];
                *(float2*)(o0 + c) = make_float2((acc2[f][0] - muA) * rsdA * g0 + be0,
                                                 (acc2[f][1] - muA) * rsdA * g1 + be1);
                *(float2*)(o1 + c) = make_float2((acc2[f][2] - muB) * rsdB * g0 + be0,
                                                 (acc2[f][3] - muB) * rsdB * g1 + be1);
            }
        }
    }
#undef PAIRBAR
}

// ---------------------------------------------------------------------------
extern "C" void kernel_launch(void* const* d_in, const int* in_sizes, int n_in,
                              void* d_out, int out_size)
{
    const float* q     = (const float*)d_in[0];
    const float* k     = (const float*)d_in[1];
    const float* v     = (const float*)d_in[2];
    const float* proj  = (const float*)d_in[3];
    const float* gamma = (const float*)d_in[4];
    const float* beta  = (const float*)d_in[5];
    float* out = (float*)d_out;

    cudaFuncSetAttribute(fa_pass1, cudaFuncAttributeMaxDynamicSharedMemorySize, P1_BYTES);
    cudaFuncSetAttribute(fa_pass2, cudaFuncAttributeMaxDynamicSharedMemorySize, P2_BYTES);

    fa_setup<<<1, 256>>>(proj);
    fa_pass1<<<dim3(16, BHV), 256, P1_BYTES>>>(k, v, gamma, beta);
    fa_reduce<<<128, 256>>>();
    fa_pass2<<<dim3(16, BHV), 256, P2_BYTES>>>(q, gamma, beta, out);
}

// round 16
// speedup vs baseline: 1.2602x; 1.0017x over previous
#include <cuda_runtime.h>
#include <cuda_bf16.h>
#include <cuda_fp16.h>
#include <cstdint>

#define TV 8192
#define BHV 32
#define LN_EPS 1e-5f
#define DEN_EPS 1e-6f
#define RSB 144     // plane row stride bytes (72 fp16)
#define TPC 8       // 64-token tiles per CTA

// Scratch (allocation-free)
__device__ uint32_t g_kp[(size_t)BHV * TV * 32];            // 32 MB kp 2xbf16 [bh][t][m/2] (denominator)
__device__ float    g_part[(size_t)BHV * 16 * 4096];        // 8 MB partial kv
__device__ __align__(16) uint32_t g_pjh[2304];              // packed fp16 proj plane [m][n]
__device__ __align__(16) uint32_t g_kvh[(size_t)BHV * 2304];// packed fp16 kv plane per bh

// ---------------- helpers ----------------
__device__ __forceinline__ uint32_t smem_u32(const void* p) {
    uint32_t a;
    asm("{ .reg .u64 t; cvta.to.shared.u64 t, %1; cvt.u32.u64 %0, t; }" : "=r"(a) : "l"(p));
    return a;
}
__device__ __forceinline__ float featexp(float x) {
    return __expf(fminf(fmaxf(x, -15.f), 15.f)) * 0.1f;
}
__device__ __forceinline__ float qred(float v) {
    v += __shfl_xor_sync(0xffffffffu, v, 1);
    v += __shfl_xor_sync(0xffffffffu, v, 2);
    return v;
}
__device__ __forceinline__ uint32_t pack2b(float x, float y) {
    __nv_bfloat162 b = __floats2bfloat162_rn(x, y);
    return *(uint32_t*)&b;
}
__device__ __forceinline__ float2 unpk2b(uint32_t p) {
    __nv_bfloat162 b = *(__nv_bfloat162*)&p;
    return make_float2(__bfloat162float(b.x), __bfloat162float(b.y));
}
__device__ __forceinline__ uint32_t pack2h(float x, float y) {
    __half2 h = __floats2half2_rn(x, y);
    return *(uint32_t*)&h;
}
__device__ __forceinline__ void ldsm4(uint32_t* r, uint32_t a) {
    asm volatile("ldmatrix.sync.aligned.m8n8.x4.shared.b16 {%0,%1,%2,%3}, [%4];"
        : "=r"(r[0]), "=r"(r[1]), "=r"(r[2]), "=r"(r[3]) : "r"(a));
}
__device__ __forceinline__ void ldsm4t(uint32_t* r, uint32_t a) {
    asm volatile("ldmatrix.sync.aligned.m8n8.x4.trans.shared.b16 {%0,%1,%2,%3}, [%4];"
        : "=r"(r[0]), "=r"(r[1]), "=r"(r[2]), "=r"(r[3]) : "r"(a));
}
__device__ __forceinline__ void mma_f16(float* c, const uint32_t* a, uint32_t b0, uint32_t b1) {
    asm("mma.sync.aligned.m16n8k16.row.col.f32.f16.f16.f32 "
        "{%0,%1,%2,%3},{%4,%5,%6,%7},{%8,%9},{%0,%1,%2,%3};"
        : "+f"(c[0]), "+f"(c[1]), "+f"(c[2]), "+f"(c[3])
        : "r"(a[0]), "r"(a[1]), "r"(a[2]), "r"(a[3]), "r"(b0), "r"(b1));
}
__device__ __forceinline__ void ln16(float* x, const float* GB, int c0) {
    float s = 0.f, ss = 0.f;
#pragma unroll
    for (int j = 0; j < 16; j++) { s += x[j]; ss += x[j] * x[j]; }
    s = qred(s); ss = qred(ss);
    float mu = s * (1.f / 64.f);
    float rstd = rsqrtf(ss * (1.f / 64.f) - mu * mu + LN_EPS);
#pragma unroll
    for (int j = 0; j < 16; j++)
        x[j] = (x[j] - mu) * rstd * GB[c0 + j] + GB[64 + c0 + j];
}
__device__ __forceinline__ void pack16vh(const float* x, float sc, uint4& v0, uint4& v1) {
    v0.x = pack2h(x[0] * sc, x[1] * sc);   v0.y = pack2h(x[2] * sc, x[3] * sc);
    v0.z = pack2h(x[4] * sc, x[5] * sc);   v0.w = pack2h(x[6] * sc, x[7] * sc);
    v1.x = pack2h(x[8] * sc, x[9] * sc);   v1.y = pack2h(x[10] * sc, x[11] * sc);
    v1.z = pack2h(x[12] * sc, x[13] * sc); v1.w = pack2h(x[14] * sc, x[15] * sc);
}

// pass1 byte offsets (EXACT R15)
#define P1_KN  0
#define P1_KP  9216
#define P1_PJ  18432
#define P1_VT  27648
#define P1_GB  36864
#define P1_BYTES 37376
// pass2 byte offsets (R15 + separate QP plane; B2 removed)
#define P2_QN  0       // qn plane (LN output)
#define P2_QP  9216    // qp plane (epi3 output) -- double buffer
#define P2_PJ  18432
#define P2_KV  27648
#define P2_DEN 36864
#define P2_PD  37376   // 256 x float2
#define P2_GB  39424
#define P2_BYTES 39936

// ---------------------------------------------------------------------------
extern "C" __global__ void fa_setup(const float* __restrict__ proj)
{
    const int tid = threadIdx.x;
    for (int i = tid; i < 2048; i += 256) {
        int m = i & 63, nw = i >> 6;
        g_pjh[m * 36 + nw] = pack2h(proj[(2 * nw) * 64 + m], proj[(2 * nw + 1) * 64 + m]);
    }
}

// ---------------------------------------------------------------------------
// Pass 1: EXACT R15 (proven). CTA = 512 tokens, 2 syncs per tile, fp16 ops.
// ---------------------------------------------------------------------------
extern "C" __global__ void __launch_bounds__(256, 4) fa_pass1(
    const float* __restrict__ k, const float* __restrict__ v,
    const float* __restrict__ gamma, const float* __restrict__ beta)
{
    extern __shared__ char sm[];
    const uint32_t sb = smem_u32(sm);
    float* GB = (float*)(sm + P1_GB);

    const int tid = threadIdx.x, lane = tid & 31, wid = tid >> 5;
    const int bh = blockIdx.y, bx = blockIdx.x;
    const int t = tid >> 2, c0 = (tid & 3) * 16;

    if (tid < 64) GB[tid] = gamma[tid];
    else if (tid < 128) GB[tid] = beta[tid - 64];
    {
        const uint4* src = (const uint4*)g_pjh;
        uint4* dst = (uint4*)(sm + P1_PJ);
        for (int i = tid; i < 576; i += 256) dst[i] = src[i];
    }
    __syncthreads();

    const int r = lane >> 2, qk = (lane & 3) * 2;
    const int mb = wid & 3, nh = wid >> 2;
    const int tr = mb * 16 + r;
    const int l7 = lane & 7, l8 = (lane >> 3) & 1, l16 = (lane >> 4) & 1;

    const uint32_t aG1 = sb + P1_KN + (mb * 16 + l7 + l8 * 8) * RSB + l16 * 16;
    const uint32_t bG1 = sb + P1_PJ + (nh * 32 + l7 + l16 * 8) * RSB + l8 * 16;
    const uint32_t aG2 = sb + P1_KP + (l7 + l16 * 8) * RSB + (mb * 16 + l8 * 8) * 2;
    const uint32_t bG2 = sb + P1_VT + (l7 + l8 * 8) * RSB + (nh * 32 + l16 * 8) * 2;

    char* lnst = sm + (size_t)t * RSB + c0 * 2;

    float acc2[4][4];
#pragma unroll
    for (int f = 0; f < 4; f++)
#pragma unroll
        for (int j = 0; j < 4; j++) acc2[f][j] = 0.f;

    for (int it = 0; it < TPC; ++it) {
        const int t0 = (bx * TPC + it) * 64;
        const float* kr = k + ((size_t)(bh * TV + t0 + t)) * 64 + c0;
        const float* vr = v + ((size_t)(bh * TV + t0 + t)) * 64 + c0;

        // ---- Phase 1: LN(k)+L2 -> KN (fp16); prefetch v ----
        {
            asm volatile("prefetch.global.L2 [%0];" :: "l"(vr));
            float xk[16];
#pragma unroll
            for (int i = 0; i < 4; i++) *(float4*)(xk + 4 * i) = *(const float4*)(kr + 4 * i);
            ln16(xk, GB, c0);
            float n2 = 0.f;
#pragma unroll
            for (int j = 0; j < 16; j++) n2 += xk[j] * xk[j];
            n2 = qred(n2);
            float inv = 1.f / fmaxf(sqrtf(n2), 1e-12f);
            uint4 v0, v1;
            pack16vh(xk, inv, v0, v1);
            *(uint4*)(lnst + P1_KN) = v0;
            *(uint4*)(lnst + P1_KN + 16) = v1;
        }
        __syncthreads();   // S1

        // ---- Phase 2: GEMM1 fp16 ----
        float acc[4][4];
#pragma unroll
        for (int f = 0; f < 4; f++)
#pragma unroll
            for (int j = 0; j < 4; j++) acc[f][j] = 0.f;
#pragma unroll
        for (int ks = 0; ks < 4; ks++) {
            uint32_t Ah[4];
            ldsm4(Ah, aG1 + ks * 32);
#pragma unroll
            for (int f2 = 0; f2 < 2; f2++) {
                uint32_t Bh[4];
                ldsm4(Bh, bG1 + f2 * 16 * RSB + ks * 32);
                mma_f16(acc[f2 * 2],     Ah, Bh[0], Bh[1]);
                mma_f16(acc[f2 * 2 + 1], Ah, Bh[2], Bh[3]);
            }
        }

        // ---- Phase 3: kp -> g_kp (bf16) + KP plane (fp16) ----
        {
            uint32_t* gkp = g_kp + ((size_t)bh * TV + t0) * 32;
#pragma unroll
            for (int f = 0; f < 4; f++) {
                float x0 = featexp(acc[f][0]), x1 = featexp(acc[f][1]);
                float x2 = featexp(acc[f][2]), x3 = featexp(acc[f][3]);
                int c = nh * 32 + f * 8 + qk;
                gkp[tr * 32 + (c >> 1)] = pack2b(x0, x1);
                gkp[(tr + 8) * 32 + (c >> 1)] = pack2b(x2, x3);
                *(uint32_t*)(sm + P1_KP + tr * RSB + c * 2) = pack2h(x0, x1);
                *(uint32_t*)(sm + P1_KP + (tr + 8) * RSB + c * 2) = pack2h(x2, x3);
            }
        }

        // ---- Phase 4: LN(v) -> VT fp16 ----
        {
            float xv[16];
#pragma unroll
            for (int i = 0; i < 4; i++) *(float4*)(xv + 4 * i) = *(const float4*)(vr + 4 * i);
            ln16(xv, GB, c0);
            uint4 v0, v1;
            pack16vh(xv, 1.f, v0, v1);
            *(uint4*)(lnst + P1_VT) = v0;
            *(uint4*)(lnst + P1_VT + 16) = v1;
        }
        __syncthreads();   // S2

        // ---- Phase 5: GEMM2 fp16 ----
#pragma unroll
        for (int ks = 0; ks < 4; ks++) {
            uint32_t Ah[4];
            ldsm4t(Ah, aG2 + ks * 16 * RSB);
#pragma unroll
            for (int f2 = 0; f2 < 2; f2++) {
                uint32_t Bh[4];
                ldsm4t(Bh, bG2 + f2 * 32 + ks * 16 * RSB);
                mma_f16(acc2[f2 * 2],     Ah, Bh[0], Bh[1]);
                mma_f16(acc2[f2 * 2 + 1], Ah, Bh[2], Bh[3]);
            }
        }
    }

    float* gp = g_part + (size_t)(bh * 16 + bx) * 4096;
#pragma unroll
    for (int f = 0; f < 4; f++) {
        int n = nh * 32 + f * 8 + qk;
        *(float2*)(gp + tr * 64 + n) = make_float2(acc2[f][0], acc2[f][1]);
        *(float2*)(gp + (tr + 8) * 64 + n) = make_float2(acc2[f][2], acc2[f][3]);
    }
}

// ---------------------------------------------------------------------------
extern "C" __global__ void __launch_bounds__(256) fa_reduce()
{
    const int tid = blockIdx.x * 256 + threadIdx.x;
    const int bh = tid >> 10, e4 = tid & 1023;
    const float4* p = (const float4*)(g_part + (size_t)bh * 16 * 4096) + e4;
    float4 s = make_float4(0.f, 0.f, 0.f, 0.f);
#pragma unroll
    for (int c = 0; c < 16; ++c) {
        float4 a = p[(size_t)c * 1024];
        s.x += a.x; s.y += a.y; s.z += a.z; s.w += a.w;
    }
    s.x *= 0.1f; s.y *= 0.1f; s.z *= 0.1f; s.w *= 0.1f;
    const int m = e4 >> 4, n0 = (e4 & 15) * 4;
    const int base = bh * 2304 + m * 36 + (n0 >> 1);
    g_kvh[base]     = pack2h(s.x, s.y);
    g_kvh[base + 1] = pack2h(s.z, s.w);
}

// ---------------------------------------------------------------------------
// Pass 2: R15 pairwise structure + double-buffered qp plane -> 3 barriers/tile.
// Cross-warp W/R audit (pair-local rows throughout):
//   LN W[QN]    vs GEMM3 R[QN]      : B1
//   epi3 W[QP]  vs GEMM4 R[QP]      : B3   (no barrier GEMM3->epi3: QP != QN)
//   epi3 W[DEN] vs epi4 R[DEN]      : B3
//   epi4 W[PD]  vs finalLN R[PD]    : B4
//   LN(it+1) W[QN] vs GEMM3(it) R[QN]: B3(it)+B4(it)
//   epi3(it+1) W[QP] vs GEMM4(it) R[QP]: B4(it)+B1(it+1)
// ---------------------------------------------------------------------------
extern "C" __global__ void __launch_bounds__(256, 4) fa_pass2(
    const float* __restrict__ q, const float* __restrict__ gamma,
    const float* __restrict__ beta, float* __restrict__ out)
{
    extern __shared__ char sm[];
    const uint32_t sb = smem_u32(sm);
    float*  DEN = (float*)(sm + P2_DEN);
    float2* PD  = (float2*)(sm + P2_PD);
    float*  GB  = (float*)(sm + P2_GB);

    const int tid = threadIdx.x, lane = tid & 31, wid = tid >> 5;
    const int bh = blockIdx.y, bx = blockIdx.x;
    const int mb = wid & 3, nh = wid >> 2;
    const int t = mb * 16 + nh * 8 + (lane >> 2);
    const int c0 = (lane & 3) * 16;

    if (tid < 64) GB[tid] = gamma[tid];
    else if (tid < 128) GB[tid] = beta[tid - 64];
    {
        const uint4* src = (const uint4*)g_pjh;
        uint4* dst = (uint4*)(sm + P2_PJ);
        for (int i = tid; i < 576; i += 256) dst[i] = src[i];
        const uint4* kh = (const uint4*)(g_kvh + bh * 2304);
        uint4* dh = (uint4*)(sm + P2_KV);
        for (int i = tid; i < 576; i += 256) dh[i] = kh[i];
    }
    __syncthreads();

    const int r = lane >> 2, qk = (lane & 3) * 2;
    const int tr = mb * 16 + r;
    const int l7 = lane & 7, l8 = (lane >> 3) & 1, l16 = (lane >> 4) & 1;

    const uint32_t aG3 = sb + P2_QN + (mb * 16 + l7 + l8 * 8) * RSB + l16 * 16;
    const uint32_t aG4 = sb + P2_QP + (mb * 16 + l7 + l8 * 8) * RSB + l16 * 16;
    const uint32_t bG3 = sb + P2_PJ + (nh * 32 + l7 + l16 * 8) * RSB + l8 * 16;
    const uint32_t bG4 = sb + P2_KV + (l7 + l8 * 8) * RSB + (nh * 32 + l16 * 8) * 2;
    char* lnst = sm + P2_QN + (size_t)t * RSB + c0 * 2;

#define PAIRBAR() asm volatile("bar.sync %0, 64;" :: "r"(mb + 1) : "memory")

    for (int it = 0; it < TPC; ++it) {
        const int t0 = (bx * TPC + it) * 64;
        float x[16];

        // ---- LN + L2 of q -> QN fp16 ----
        {
            const float* qr = q + ((size_t)(bh * TV + t0 + t)) * 64 + c0;
#pragma unroll
            for (int i = 0; i < 4; i++) *(float4*)(x + 4 * i) = *(const float4*)(qr + 4 * i);
            ln16(x, GB, c0);
            float n2 = 0.f;
#pragma unroll
            for (int j = 0; j < 16; j++) n2 += x[j] * x[j];
            n2 = qred(n2);
            float inv = 1.f / fmaxf(sqrtf(n2), 1e-12f);
            uint4 v0, v1;
            pack16vh(x, inv, v0, v1);
            *(uint4*)(lnst) = v0;
            *(uint4*)(lnst + 16) = v1;
        }
        PAIRBAR();   // B1

        // ---- GEMM3 fp16: D3[t][m] = QN @ PJ^T ----
        float acc[4][4];
#pragma unroll
        for (int f = 0; f < 4; f++)
#pragma unroll
            for (int j = 0; j < 4; j++) acc[f][j] = 0.f;
#pragma unroll
        for (int ks = 0; ks < 4; ks++) {
            uint32_t Ah[4];
            ldsm4(Ah, aG3 + ks * 32);
#pragma unroll
            for (int f2 = 0; f2 < 2; f2++) {
                uint32_t Bh[4];
                ldsm4(Bh, bG3 + f2 * 16 * RSB + ks * 32);
                mma_f16(acc[f2 * 2],     Ah, Bh[0], Bh[1]);
                mma_f16(acc[f2 * 2 + 1], Ah, Bh[2], Bh[3]);
            }
        }

        // ---- epi3 (no barrier needed): qp -> QP plane; denom vs g_kp ----
        {
            const uint32_t* gkp = g_kp + ((size_t)bh * TV + t0) * 32;
            float den0 = 0.f, den1 = 0.f;
#pragma unroll
            for (int f = 0; f < 4; f++) {
                float x0 = featexp(acc[f][0]), x1 = featexp(acc[f][1]);
                float x2 = featexp(acc[f][2]), x3 = featexp(acc[f][3]);
                int c = nh * 32 + f * 8 + qk;
                *(uint32_t*)(sm + P2_QP + tr * RSB + c * 2) = pack2h(x0, x1);
                *(uint32_t*)(sm + P2_QP + (tr + 8) * RSB + c * 2) = pack2h(x2, x3);
                float2 k0 = unpk2b(gkp[tr * 32 + (c >> 1)]);
                float2 k1 = unpk2b(gkp[(tr + 8) * 32 + (c >> 1)]);
                den0 += x0 * k0.x + x1 * k0.y;
                den1 += x2 * k1.x + x3 * k1.y;
            }
            den0 = qred(den0);
            den1 = qred(den1);
            if ((lane & 3) == 0) { DEN[nh * 64 + tr] = den0; DEN[nh * 64 + tr + 8] = den1; }
        }
        PAIRBAR();   // B3

        // ---- GEMM4 fp16: D4[t][n] = qp @ kv ----
        float acc2[4][4];
#pragma unroll
        for (int f = 0; f < 4; f++)
#pragma unroll
            for (int j = 0; j < 4; j++) acc2[f][j] = 0.f;
#pragma unroll
        for (int ks = 0; ks < 4; ks++) {
            uint32_t Ah[4];
            ldsm4(Ah, aG4 + ks * 32);
#pragma unroll
            for (int f2 = 0; f2 < 2; f2++) {
                uint32_t Bh[4];
                ldsm4t(Bh, bG4 + f2 * 32 + ks * 16 * RSB);
                mma_f16(acc2[f2 * 2],     Ah, Bh[0], Bh[1]);
                mma_f16(acc2[f2 * 2 + 1], Ah, Bh[2], Bh[3]);
            }
        }

        // ---- epilogue4: scale by 0.1/den; partial row stats -> PD ----
        {
            float s0 = 0.1f / fmaxf(DEN[tr] + DEN[64 + tr], DEN_EPS);
            float s1 = 0.1f / fmaxf(DEN[tr + 8] + DEN[64 + tr + 8], DEN_EPS);
            float sA = 0.f, ssA = 0.f, sB = 0.f, ssB = 0.f;
#pragma unroll
            for (int f = 0; f < 4; f++) {
                acc2[f][0] *= s0; acc2[f][1] *= s0;
                acc2[f][2] *= s1; acc2[f][3] *= s1;
                sA += acc2[f][0] + acc2[f][1];
                ssA += acc2[f][0] * acc2[f][0] + acc2[f][1] * acc2[f][1];
                sB += acc2[f][2] + acc2[f][3];
                ssB += acc2[f][2] * acc2[f][2] + acc2[f][3] * acc2[f][3];
            }
            sA = qred(sA); ssA = qred(ssA);
            sB = qred(sB); ssB = qred(ssB);
            if ((lane & 3) == 0) {
                PD[nh * 128 + tr] = make_float2(sA, ssA);
                PD[nh * 128 + tr + 8] = make_float2(sB, ssB);
            }
        }
        PAIRBAR();   // B4

        // ---- final LN from registers; direct gmem store ----
        {
            float2 a0 = PD[tr],     b0 = PD[128 + tr];
            float2 a1 = PD[tr + 8], b1 = PD[128 + tr + 8];
            float muA = (a0.x + b0.x) * (1.f / 64.f);
            float rsdA = rsqrtf((a0.y + b0.y) * (1.f / 64.f) - muA * muA + LN_EPS);
            float muB = (a1.x + b1.x) * (1.f / 64.f);
            float rsdB = rsqrtf((a1.y + b1.y) * (1.f / 64.f) - muB * muB + LN_EPS);
            float* o0 = out + ((size_t)(bh * TV + t0 + tr)) * 64;
            float* o1 = out + ((size_t)(bh * TV + t0 + tr + 8)) * 64;
#pragma unroll
            for (int f = 0; f < 4; f++) {
                int c = nh * 32 + f * 8 + qk;
                float g0 = GB[c], g1 = GB[c + 1];
                float be0 = GB[64 + c], be1 = GB[64 + c + 1];
                *(float2*)(o0 + c) = make_float2((acc2[f][0] - muA) * rsdA * g0 + be0,
                                                 (acc2[f][1] - muA) * rsdA * g1 + be1);
                *(float2*)(o1 + c) = make_float2((acc2[f][2] - muB) * rsdB * g0 + be0,
                                                 (acc2[f][3] - muB) * rsdB * g1 + be1);
            }
        }
    }
#undef PAIRBAR
}

// ---------------------------------------------------------------------------
extern "C" void kernel_launch(void* const* d_in, const int* in_sizes, int n_in,
                              void* d_out, int out_size)
{
    const float* q     = (const float*)d_in[0];
    const float* k     = (const float*)d_in[1];
    const float* v     = (const float*)d_in[2];
    const float* proj  = (const float*)d_in[3];
    const float* gamma = (const float*)d_in[4];
    const float* beta  = (const float*)d_in[5];
    float* out = (float*)d_out;

    cudaFuncSetAttribute(fa_pass1, cudaFuncAttributeMaxDynamicSharedMemorySize, P1_BYTES);
    cudaFuncSetAttribute(fa_pass2, cudaFuncAttributeMaxDynamicSharedMemorySize, P2_BYTES);

    fa_setup<<<1, 256>>>(proj);
    fa_pass1<<<dim3(16, BHV), 256, P1_BYTES>>>(k, v, gamma, beta);
    fa_reduce<<<128, 256>>>();
    fa_pass2<<<dim3(16, BHV), 256, P2_BYTES>>>(q, gamma, beta, out);
}